// round 12
// baseline (speedup 1.0000x reference)
#include <cuda_runtime.h>
#include <cuda_fp16.h>
#include <math.h>
#include <stdint.h>

#define BATCH 512
#define NP    64
#define CIN   512
#define HID   512
#define EMB   512
#define NCLS  96
#define TT    30

// ---------------- scratch (device globals; no allocations) ----------------
__device__ float  g_featcvt[(size_t)BATCH * NP * CIN];  // tf32-rounded features
__device__ __half g_feats_h[(size_t)BATCH * NP * HID];  // fp16 (attention only)
__device__ float  g_emb[(size_t)TT * BATCH * EMB];      // tf32-rounded
__device__ float  g_lpre[(size_t)TT * BATCH * HID];     // fp32
__device__ float  g_xpre[(size_t)TT * BATCH * HID];     // tf32-rounded
__device__ float  g_hist[(size_t)TT * BATCH * HID];     // tf32-rounded h history
__device__ float  g_hbuf[2][BATCH * HID];               // tf32-rounded h
__device__ float  g_c[BATCH * HID];
__device__ float  g_logits2[2][BATCH * HID];            // split-K partials
__device__ float  g_ctx[BATCH * HID];                   // tf32-rounded
__device__ float  g_Wih[(size_t)2048 * 512];            // tf32 Wih gate-interleaved
__device__ float  g_Wg3[(size_t)2048 * 1536];           // tf32 [W1|Whh|Wih] gate-interleaved
__device__ float  g_bg[2048];
__device__ float  g_Wlx[(size_t)1024 * 512];            // tf32 [WaE ; WcC]
__device__ float  g_blx[1024];
__device__ float  g_wcct[(size_t)512 * 512];            // tf32 WcC^T
#define OFF_WFC 0
#define OFF_WA  (512 * 512)
#define OFF_WC  (OFF_WA + 512 * 1024)
#define OFF_WO  (OFF_WC + 512 * 1024)
#define WCVT_N  (OFF_WO + 96 * 512)
__device__ float g_wcvt[WCVT_N];

__device__ __forceinline__ float f2tf32f(float f) {
    uint32_t r;
    asm("cvt.rna.tf32.f32 %0, %1;" : "=r"(r) : "f"(f));
    return __uint_as_float(r);
}
__device__ __forceinline__ float fsig(float x) {
    return __fdividef(1.f, 1.f + __expf(-x));
}
__device__ __forceinline__ float ftanh(float x) {
    x = fminf(fmaxf(x, -15.f), 15.f);
    float t = __expf(2.f * x);
    return __fdividef(t - 1.f, t + 1.f);
}
__device__ __forceinline__ void cp16(uint32_t dst, const void* src) {
    asm volatile("cp.async.cg.shared.global [%0], [%1], 16;" :: "r"(dst), "l"(src));
}
__device__ __forceinline__ void cp_commit() { asm volatile("cp.async.commit_group;"); }
template <int N>
__device__ __forceinline__ void cp_wait() { asm volatile("cp.async.wait_group %0;" :: "n"(N)); }

// ------------- TF32 GEMM, cp.async pipeline + frag double-buffer ----------
// A is up to THREE K-segments: [0,K1) from A1, [K1,K2) from A2, [K2,K) from A3.
// B rows at B + n*ldb + boff.
// MODE 0: float C = acc (+bias)(+addend[ldadd])
// MODE 1: fused LSTM epilogue (bias = g_bg lookup); writes g_c, h_out, g_hist
// MODE 2: permuted fp32 out-projection write
// MODE 4: half C = acc + bias
// MODE 5: tf32-rounded float C = acc (+bias)(+addend)
// SPLITK: blockIdx.z selects K-half (A1/B cols shift 256; z=1 drops addend,
//         writes C + BATCH*HID). K passed as 256, K1=K2=512.
template <int BM, int BN, int BK, int WARPS_M, int WARPS_N, int MODE, int SPLITK>
__global__ void __launch_bounds__(WARPS_M * WARPS_N * 32)
gemm(const float* __restrict__ A1, int lda1, int K1,
     const float* __restrict__ A2, int lda2, int K2,
     const float* __restrict__ A3, int lda3, int K,
     const float* __restrict__ B, int ldb, int boff,
     const float* __restrict__ bias,
     const float* __restrict__ addend, int ldadd,
     void* __restrict__ Cv, int ldc, float* __restrict__ h_out, int t)
{
    constexpr int S = 3, PAD = 4, ROWF = BK + PAD;
    constexpr int THREADS = WARPS_M * WARPS_N * 32;
    constexpr int WM = BM / WARPS_M, WN = BN / WARPS_N;
    constexpr int M_SUB = WM / 16, N_SUB = WN / 8;
    constexpr int BK4 = BK / 4;
    constexpr int AV = (BM * BK) / (4 * THREADS);
    constexpr int BV = (BN * BK) / (4 * THREADS);
    constexpr int ASTR = BM * ROWF;
    constexpr int BSTR = BN * ROWF;

    if constexpr (SPLITK) {
        if (blockIdx.z) {
            A1 += 256;
            boff += 256;
            Cv = (void*)((float*)Cv + (size_t)BATCH * HID);
            addend = nullptr;
        }
    }

    extern __shared__ float sh[];
    const uint32_t smem_u = (uint32_t)__cvta_generic_to_shared(sh);
    const int bm = blockIdx.y * BM, bn = blockIdx.x * BN;
    const int tid = threadIdx.x;
    const int wid = tid >> 5, lane = tid & 31;
    const int gid = lane >> 2, tig = lane & 3;
    const int warpM = wid % WARPS_M, warpN = wid / WARPS_M;

    float acc[M_SUB][N_SUB][4];
#pragma unroll
    for (int i = 0; i < M_SUB; i++)
#pragma unroll
        for (int j = 0; j < N_SUB; j++)
#pragma unroll
            for (int q = 0; q < 4; q++) acc[i][j][q] = 0.f;

    auto issue = [&](int stg, int k0) {
        const float* Ap; int lda, kc;
        if (k0 < K1)      { Ap = A1; lda = lda1; kc = k0; }
        else if (k0 < K2) { Ap = A2; lda = lda2; kc = k0 - K1; }
        else              { Ap = A3; lda = lda3; kc = k0 - K2; }
        uint32_t ab = smem_u + (uint32_t)(stg * ASTR) * 4u;
#pragma unroll
        for (int i = 0; i < AV; i++) {
            int idx = tid + i * THREADS;
            int r = idx / BK4, c4 = idx % BK4;
            cp16(ab + (uint32_t)(r * ROWF + c4 * 4) * 4u,
                 Ap + (size_t)(bm + r) * lda + kc + c4 * 4);
        }
        uint32_t bb = smem_u + (uint32_t)(S * ASTR + stg * BSTR) * 4u;
#pragma unroll
        for (int i = 0; i < BV; i++) {
            int idx = tid + i * THREADS;
            int r = idx / BK4, c4 = idx % BK4;
            cp16(bb + (uint32_t)(r * ROWF + c4 * 4) * 4u,
                 B + (size_t)(bn + r) * ldb + boff + k0 + c4 * 4);
        }
    };

    const int NK = K / BK;
    issue(0, 0);  cp_commit();
    issue(1, BK); cp_commit();

    uint32_t afr[2][M_SUB][4];
    uint32_t bfr[2][N_SUB][2];
    auto ldfrag = [&](const float* As, const float* Bs, int buf, int kb) {
#pragma unroll
        for (int mt = 0; mt < M_SUB; mt++) {
            int r0 = warpM * WM + mt * 16 + gid;
            afr[buf][mt][0] = __float_as_uint(As[r0 * ROWF + kb + tig]);
            afr[buf][mt][1] = __float_as_uint(As[(r0 + 8) * ROWF + kb + tig]);
            afr[buf][mt][2] = __float_as_uint(As[r0 * ROWF + kb + tig + 4]);
            afr[buf][mt][3] = __float_as_uint(As[(r0 + 8) * ROWF + kb + tig + 4]);
        }
#pragma unroll
        for (int nt = 0; nt < N_SUB; nt++) {
            int c0 = warpN * WN + nt * 8 + gid;
            bfr[buf][nt][0] = __float_as_uint(Bs[c0 * ROWF + kb + tig]);
            bfr[buf][nt][1] = __float_as_uint(Bs[c0 * ROWF + kb + tig + 4]);
        }
    };

    for (int k = 0; k < NK; k++) {
        cp_wait<1>();
        __syncthreads();
        int kn = k + S - 1;
        if (kn < NK) issue(kn % S, kn * BK);
        cp_commit();
        const float* As = sh + (k % S) * ASTR;
        const float* Bs = sh + S * ASTR + (k % S) * BSTR;
        ldfrag(As, Bs, 0, 0);
#pragma unroll
        for (int ks = 0; ks < BK / 8; ks++) {
            const int cur = ks & 1, nxt = cur ^ 1;
            if (ks < BK / 8 - 1) ldfrag(As, Bs, nxt, (ks + 1) * 8);
#pragma unroll
            for (int nt = 0; nt < N_SUB; nt++) {
#pragma unroll
                for (int mt = 0; mt < M_SUB; mt++) {
                    asm volatile(
                        "mma.sync.aligned.m16n8k8.row.col.f32.tf32.tf32.f32 "
                        "{%0,%1,%2,%3}, {%4,%5,%6,%7}, {%8,%9}, {%0,%1,%2,%3};"
                        : "+f"(acc[mt][nt][0]), "+f"(acc[mt][nt][1]),
                          "+f"(acc[mt][nt][2]), "+f"(acc[mt][nt][3])
                        : "r"(afr[cur][mt][0]), "r"(afr[cur][mt][1]),
                          "r"(afr[cur][mt][2]), "r"(afr[cur][mt][3]),
                          "r"(bfr[cur][nt][0]), "r"(bfr[cur][nt][1]));
                }
            }
        }
    }

    if constexpr (MODE == 0 || MODE == 5) {
        float* C = (float*)Cv;
#pragma unroll
        for (int mt = 0; mt < M_SUB; mt++) {
#pragma unroll
            for (int nt = 0; nt < N_SUB; nt++) {
                int row0 = bm + warpM * WM + mt * 16 + gid;
                int col  = bn + warpN * WN + nt * 8 + 2 * tig;
                float bx = 0.f, by = 0.f;
                if (bias) { float2 bv = *(const float2*)(bias + col); bx = bv.x; by = bv.y; }
                float a0x = 0.f, a0y = 0.f, a1x = 0.f, a1y = 0.f;
                if (addend) {
                    float2 v = *(const float2*)(addend + (size_t)row0 * ldadd + col);
                    a0x = v.x; a0y = v.y;
                    float2 w = *(const float2*)(addend + (size_t)(row0 + 8) * ldadd + col);
                    a1x = w.x; a1y = w.y;
                }
                float2 v0 = { acc[mt][nt][0] + bx + a0x, acc[mt][nt][1] + by + a0y };
                float2 v1 = { acc[mt][nt][2] + bx + a1x, acc[mt][nt][3] + by + a1y };
                if (MODE == 5) {
                    v0.x = f2tf32f(v0.x); v0.y = f2tf32f(v0.y);
                    v1.x = f2tf32f(v1.x); v1.y = f2tf32f(v1.y);
                }
                *(float2*)(C + (size_t)row0 * ldc + col) = v0;
                *(float2*)(C + (size_t)(row0 + 8) * ldc + col) = v1;
            }
        }
    } else if constexpr (MODE == 4) {
        __half* C = (__half*)Cv;
#pragma unroll
        for (int mt = 0; mt < M_SUB; mt++) {
#pragma unroll
            for (int nt = 0; nt < N_SUB; nt++) {
                int row0 = bm + warpM * WM + mt * 16 + gid;
                int col  = bn + warpN * WN + nt * 8 + 2 * tig;
                float2 bv = *(const float2*)(bias + col);
                *(__half2*)(C + (size_t)row0 * ldc + col) =
                    __floats2half2_rn(acc[mt][nt][0] + bv.x, acc[mt][nt][1] + bv.y);
                *(__half2*)(C + (size_t)(row0 + 8) * ldc + col) =
                    __floats2half2_rn(acc[mt][nt][2] + bv.x, acc[mt][nt][3] + bv.y);
            }
        }
    } else if constexpr (MODE == 2) {
        float* C = (float*)Cv;
#pragma unroll
        for (int mt = 0; mt < M_SUB; mt++) {
#pragma unroll
            for (int nt = 0; nt < N_SUB; nt++) {
                int row0 = bm + warpM * WM + mt * 16 + gid;
                int col  = bn + warpN * WN + nt * 8 + 2 * tig;
                float2 bv = *(const float2*)(bias + col);
#pragma unroll
                for (int rr = 0; rr < 2; rr++) {
                    int r = row0 + rr * 8;
                    int tt = r >> 9, b = r & 511;
                    *(float2*)(C + ((size_t)b * TT + tt) * NCLS + col) =
                        make_float2(acc[mt][nt][rr * 2 + 0] + bv.x,
                                    acc[mt][nt][rr * 2 + 1] + bv.y);
                }
            }
        }
    } else {  // MODE 1: fused LSTM epilogue
        float* Cs = sh;
        constexpr int CPAD = 4;
        __syncthreads();
#pragma unroll
        for (int mt = 0; mt < M_SUB; mt++) {
#pragma unroll
            for (int nt = 0; nt < N_SUB; nt++) {
                int rl = warpM * WM + mt * 16 + gid;
                int cl = warpN * WN + nt * 8 + 2 * tig;
                float b0 = g_bg[bn + cl], b1 = g_bg[bn + cl + 1];
                Cs[rl * (BN + CPAD) + cl]           = acc[mt][nt][0] + b0;
                Cs[rl * (BN + CPAD) + cl + 1]       = acc[mt][nt][1] + b1;
                Cs[(rl + 8) * (BN + CPAD) + cl]     = acc[mt][nt][2] + b0;
                Cs[(rl + 8) * (BN + CPAD) + cl + 1] = acc[mt][nt][3] + b1;
            }
        }
        __syncthreads();
        constexpr int UNITS = BN / 4;
        for (int it = tid; it < BM * UNITS; it += THREADS) {
            int r = it / UNITS, u = it % UNITS;
            float gi = Cs[r * (BN + CPAD) + 4 * u + 0];
            float gf = Cs[r * (BN + CPAD) + 4 * u + 1];
            float gg = Cs[r * (BN + CPAD) + 4 * u + 2];
            float go = Cs[r * (BN + CPAD) + 4 * u + 3];
            int b = bm + r;
            int j = (bn >> 2) + u;
            int idx = b * HID + j;
            float c = g_c[idx];
            float cn = fsig(gf) * c + fsig(gi) * ftanh(gg);
            g_c[idx] = cn;
            float hn = f2tf32f(fsig(go) * ftanh(cn));
            h_out[idx] = hn;
            g_hist[(size_t)t * BATCH * HID + idx] = hn;
        }
    }
}

// ---- fused attention: smem-staged fp16 feats, read once -------------------
__global__ void attention_kernel(float* __restrict__ ctx)
{
    extern __shared__ __half sfeat[];   // NP*HID fp16 = 64 KB
    __shared__ float sa[HID];
    __shared__ float sw[NP];
    __shared__ float red[8];

    const int b = blockIdx.x;
    const int tid = threadIdx.x;  // 256
    const int lane = tid & 31, warp = tid >> 5;
    const __half* fb = g_feats_h + (size_t)b * NP * HID;

    {
        uint4* d4 = (uint4*)sfeat;
        const uint4* s4 = (const uint4*)fb;
#pragma unroll
        for (int i = tid; i < NP * HID / 8; i += 256) d4[i] = s4[i];
    }

    const float* l0 = g_logits2[0] + (size_t)b * HID;
    const float* l1 = g_logits2[1] + (size_t)b * HID;
    float v0 = l0[tid] + l1[tid];
    float v1 = l0[tid + 256] + l1[tid + 256];
    float m = fmaxf(v0, v1);
#pragma unroll
    for (int o = 16; o > 0; o >>= 1) m = fmaxf(m, __shfl_xor_sync(~0u, m, o));
    if (lane == 0) red[warp] = m;
    __syncthreads();
    if (tid == 0) {
        float tv = red[0];
#pragma unroll
        for (int i = 1; i < 8; i++) tv = fmaxf(tv, red[i]);
        red[0] = tv;
    }
    __syncthreads();
    m = red[0];
    __syncthreads();
    float e0 = __expf(v0 - m), e1 = __expf(v1 - m);
    float s = e0 + e1;
#pragma unroll
    for (int o = 16; o > 0; o >>= 1) s += __shfl_xor_sync(~0u, s, o);
    if (lane == 0) red[warp] = s;
    __syncthreads();
    if (tid == 0) {
        float tv = 0.f;
#pragma unroll
        for (int i = 0; i < 8; i++) tv += red[i];
        red[0] = tv;
    }
    __syncthreads();
    float inv = __fdividef(1.f, red[0]);
    sa[tid] = e0 * inv;
    sa[tid + 256] = e1 * inv;
    __syncthreads();

    for (int p = warp; p < NP; p += 8) {
        const __half2* fr = (const __half2*)(sfeat + p * HID);
        float sc = 0.f;
#pragma unroll
        for (int e = lane; e < HID / 2; e += 32) {
            float2 f = __half22float2(fr[e]);
            float2 a = *(const float2*)(sa + 2 * e);
            sc += f.x * a.x + f.y * a.y;
        }
#pragma unroll
        for (int o = 16; o > 0; o >>= 1) sc += __shfl_xor_sync(~0u, sc, o);
        if (lane == 0) sw[p] = sc;
    }
    __syncthreads();

    if (tid < 32) {
        float w0 = sw[tid], w1 = sw[tid + 32];
        float mm = fmaxf(w0, w1);
#pragma unroll
        for (int o = 16; o > 0; o >>= 1) mm = fmaxf(mm, __shfl_xor_sync(~0u, mm, o));
        float f0 = __expf(w0 - mm), f1 = __expf(w1 - mm);
        float ss = f0 + f1;
#pragma unroll
        for (int o = 16; o > 0; o >>= 1) ss += __shfl_xor_sync(~0u, ss, o);
        float iv = __fdividef(1.f, ss);
        sw[tid] = f0 * iv;
        sw[tid + 32] = f1 * iv;
    }
    __syncthreads();

    float2 a2 = {0.f, 0.f};
#pragma unroll 8
    for (int p = 0; p < NP; p++) {
        float w = sw[p];
        float2 f = __half22float2(*(const __half2*)(sfeat + p * HID + 2 * tid));
        a2.x += w * f.x;
        a2.y += w * f.y;
    }
    *(float2*)(ctx + (size_t)b * HID + 2 * tid) =
        make_float2(f2tf32f(a2.x), f2tf32f(a2.y));
}

// ---------------- setup kernels -------------------------------------------
__global__ void zero_hc_kernel()
{
    int idx = blockIdx.x * blockDim.x + threadIdx.x;
    g_hbuf[0][idx] = 0.f;
    g_c[idx] = 0.f;
}

__global__ void cvt_copy_kernel(const float* __restrict__ src, float* __restrict__ dst, int n4)
{
    for (int i = blockIdx.x * blockDim.x + threadIdx.x; i < n4; i += gridDim.x * blockDim.x) {
        float4 v = ((const float4*)src)[i];
        v.x = f2tf32f(v.x); v.y = f2tf32f(v.y);
        v.z = f2tf32f(v.z); v.w = f2tf32f(v.w);
        ((float4*)dst)[i] = v;
    }
}

// fused weight conversion into g_wcvt (all four regions)
__global__ void cvt_weights_kernel(const float* __restrict__ Wfc, const float* __restrict__ Wa,
                                   const float* __restrict__ Wc, const float* __restrict__ Wo)
{
    const int n4 = WCVT_N / 4;
    for (int i = blockIdx.x * blockDim.x + threadIdx.x; i < n4; i += gridDim.x * blockDim.x) {
        int e = i * 4;
        const float* src;
        if (e < OFF_WA)      src = Wfc + e;
        else if (e < OFF_WC) src = Wa + (e - OFF_WA);
        else if (e < OFF_WO) src = Wc + (e - OFF_WC);
        else                 src = Wo + (e - OFF_WO);
        float4 v = *(const float4*)src;
        v.x = f2tf32f(v.x); v.y = f2tf32f(v.y);
        v.z = f2tf32f(v.z); v.w = f2tf32f(v.w);
        *(float4*)(g_wcvt + e) = v;
    }
}

// gate-interleaved: g_Wih[rn,512] = Wih; g_Wg3 cols [512,1024)=Whh, [1024,1536)=Wih
__global__ void build_wg_kernel(const float* __restrict__ Wih, const float* __restrict__ Whh,
                                const float* __restrict__ bih, const float* __restrict__ bhh)
{
    int idx = blockIdx.x * blockDim.x + threadIdx.x;   // 2048*1024
    int rn = idx >> 10, k = idx & 1023;
    int j = rn >> 2, gi = rn & 3;
    int orig = gi * 512 + j;
    if (k < 512) {
        float v = f2tf32f(Wih[(size_t)orig * 512 + k]);
        g_Wih[(size_t)rn * 512 + k] = v;
        g_Wg3[(size_t)rn * 1536 + 1024 + k] = v;
    } else {
        float v = f2tf32f(Whh[(size_t)orig * 512 + (k - 512)]);
        g_Wg3[(size_t)rn * 1536 + k] = v;
    }
    if (k == 0) g_bg[rn] = bih[orig] + bhh[orig];
}

__global__ void build_wlx_kernel(const float* __restrict__ Wa, const float* __restrict__ Wc,
                                 const float* __restrict__ ba, const float* __restrict__ bc)
{
    int idx = blockIdx.x * blockDim.x + threadIdx.x;
    int rn = idx >> 9, k = idx & 511;
    float v = (rn < 512) ? Wa[(size_t)rn * 1024 + 512 + k]
                         : Wc[(size_t)(rn - 512) * 1024 + k];
    g_Wlx[idx] = f2tf32f(v);
    if (k == 0) g_blx[rn] = (rn < 512) ? ba[rn] : bc[rn - 512];
}

// WcC^T : g_wcct[q*512 + n] = tf32(Wc[n, 512+q])
__global__ void transpose_wcc_kernel(const float* __restrict__ Wc)
{
    int idx = blockIdx.x * blockDim.x + threadIdx.x;   // 512*512
    int q = idx >> 9, n = idx & 511;
    g_wcct[idx] = f2tf32f(Wc[(size_t)n * 1024 + 512 + q]);
}

__global__ void gather_emb_kernel(const int* __restrict__ targets,
                                  const float* __restrict__ table)
{
    int b = blockIdx.x;
    int t = blockIdx.y;
    int id = (t == 0) ? 0 : targets[(size_t)b * TT + (t - 1)];
    const float4* src = (const float4*)(table + (size_t)id * EMB);
    float4* dst = (float4*)(g_emb + ((size_t)t * BATCH + b) * EMB);
    int e = threadIdx.x;
    float4 v = src[e];
    v.x = f2tf32f(v.x); v.y = f2tf32f(v.y);
    v.z = f2tf32f(v.z); v.w = f2tf32f(v.w);
    dst[e] = v;
}

// ---------------- launch ----------------------------------------------------
extern "C" void kernel_launch(void* const* d_in, const int* in_sizes, int n_in,
                              void* d_out, int out_size)
{
    const float* features  = (const float*)d_in[0];
    const int*   targets   = (const int*)d_in[1];
    const float* Wfc = (const float*)d_in[3];
    const float* bfc = (const float*)d_in[4];
    const float* emb_table = (const float*)d_in[5];
    const float* Wa  = (const float*)d_in[6];
    const float* ba  = (const float*)d_in[7];
    const float* Wc  = (const float*)d_in[8];
    const float* bc  = (const float*)d_in[9];
    const float* Wih = (const float*)d_in[10];
    const float* Whh = (const float*)d_in[11];
    const float* bih = (const float*)d_in[12];
    const float* bhh = (const float*)d_in[13];
    const float* Wo  = (const float*)d_in[14];
    const float* bo  = (const float*)d_in[15];
    float* out = (float*)d_out;

    float *p_featcvt, *p_emb, *p_lpre, *p_xpre, *p_hist, *p_hbuf;
    float *p_logits2, *p_ctx, *p_Wih, *p_Wg3, *p_Wlx, *p_blx, *p_wcct, *p_wcvt;
    __half* p_feats_h;
    cudaGetSymbolAddress((void**)&p_featcvt, g_featcvt);
    cudaGetSymbolAddress((void**)&p_feats_h, g_feats_h);
    cudaGetSymbolAddress((void**)&p_emb,     g_emb);
    cudaGetSymbolAddress((void**)&p_lpre,    g_lpre);
    cudaGetSymbolAddress((void**)&p_xpre,    g_xpre);
    cudaGetSymbolAddress((void**)&p_hist,    g_hist);
    cudaGetSymbolAddress((void**)&p_hbuf,    g_hbuf);
    cudaGetSymbolAddress((void**)&p_logits2, g_logits2);
    cudaGetSymbolAddress((void**)&p_ctx,     g_ctx);
    cudaGetSymbolAddress((void**)&p_Wih,     g_Wih);
    cudaGetSymbolAddress((void**)&p_Wg3,     g_Wg3);
    cudaGetSymbolAddress((void**)&p_Wlx,     g_Wlx);
    cudaGetSymbolAddress((void**)&p_blx,     g_blx);
    cudaGetSymbolAddress((void**)&p_wcct,    g_wcct);
    cudaGetSymbolAddress((void**)&p_wcvt,    g_wcvt);

    constexpr int SM_BIG32 = 3 * (128 + 64) * 36 * 4;   // 82944  (BK=32)
    constexpr int SM_G64   = 3 * (64 + 64) * 68 * 4;    // 104448 (BK=64, gates)
    constexpr int SM_S64   = 3 * (64 + 32) * 68 * 4;    // 78336
    constexpr int SM_O64   = 3 * (128 + 32) * 68 * 4;   // 130560

    cudaFuncSetAttribute((const void*)gemm<128, 64, 32, 4, 2, 4, 0>,
                         cudaFuncAttributeMaxDynamicSharedMemorySize, SM_BIG32);
    cudaFuncSetAttribute((const void*)gemm<128, 64, 32, 4, 2, 0, 0>,
                         cudaFuncAttributeMaxDynamicSharedMemorySize, SM_BIG32);
    cudaFuncSetAttribute((const void*)gemm<128, 64, 32, 4, 2, 5, 0>,
                         cudaFuncAttributeMaxDynamicSharedMemorySize, SM_BIG32);
    cudaFuncSetAttribute((const void*)gemm<64, 32, 64, 2, 2, 0, 1>,
                         cudaFuncAttributeMaxDynamicSharedMemorySize, SM_S64);
    cudaFuncSetAttribute((const void*)gemm<64, 64, 64, 2, 2, 1, 0>,
                         cudaFuncAttributeMaxDynamicSharedMemorySize, SM_G64);
    cudaFuncSetAttribute((const void*)gemm<128, 32, 64, 4, 1, 2, 0>,
                         cudaFuncAttributeMaxDynamicSharedMemorySize, SM_O64);
    cudaFuncSetAttribute((const void*)attention_kernel,
                         cudaFuncAttributeMaxDynamicSharedMemorySize, NP * HID * 2);

    // ---------------- setup ----------------
    zero_hc_kernel<<<(BATCH * HID) / 256, 256>>>();
    build_wg_kernel<<<(2048 * 1024) / 256, 256>>>(Wih, Whh, bih, bhh);
    build_wlx_kernel<<<(1024 * 512) / 256, 256>>>(Wa, Wc, ba, bc);
    transpose_wcc_kernel<<<(512 * 512) / 256, 256>>>(Wc);
    gather_emb_kernel<<<dim3(BATCH, TT), 128>>>(targets, emb_table);
    cvt_weights_kernel<<<592, 256>>>(Wfc, Wa, Wc, Wo);
    cvt_copy_kernel<<<1024, 256>>>(features, p_featcvt, BATCH * NP * CIN / 4);

    // W1 = Wih_int @ WcC : [2048x512] tf32, into g_Wg3 cols [0,512)
    gemm<128, 64, 32, 4, 2, 5, 0><<<dim3(512 / 64, 2048 / 128), 256, SM_BIG32>>>(
        p_Wih, 512, 512, nullptr, 0, 512, nullptr, 0, 512,
        p_wcct, 512, 0, nullptr, nullptr, 0, p_Wg3, 1536, nullptr, 0);

    // feats (fp16) = features @ Wfc^T + bfc : M=32768, N=512, K=512
    gemm<128, 64, 32, 4, 2, 4, 0><<<dim3(HID / 64, (BATCH * NP) / 128), 256, SM_BIG32>>>(
        p_featcvt, CIN, CIN, nullptr, 0, CIN, nullptr, 0, CIN,
        p_wcvt + OFF_WFC, CIN, 0, bfc, nullptr, 0, p_feats_h, HID, nullptr, 0);

    // lpre = emb @ WaE^T + ba : M=15360, N=512, K=512 (fp32)
    gemm<128, 64, 32, 4, 2, 0, 0><<<dim3(512 / 64, (TT * BATCH) / 128), 256, SM_BIG32>>>(
        p_emb, EMB, EMB, nullptr, 0, EMB, nullptr, 0, EMB,
        p_Wlx, 512, 0, p_blx, nullptr, 0, p_lpre, 512, nullptr, 0);

    // xpre = emb @ WcE^T + bc : tf32-rounded (third K-segment of gates)
    gemm<128, 64, 32, 4, 2, 5, 0><<<dim3(512 / 64, (TT * BATCH) / 128), 256, SM_BIG32>>>(
        p_emb, EMB, EMB, nullptr, 0, EMB, nullptr, 0, EMB,
        p_Wlx + (size_t)512 * 512, 512, 0, p_blx + 512, nullptr, 0,
        p_xpre, 512, nullptr, 0);

    // ---------------- 30-step recurrence (3 kernels/step) ----------------
    for (int t = 0; t < TT; t++) {
        float* hr = p_hbuf + (t & 1) * BATCH * HID;
        float* hw = p_hbuf + ((t + 1) & 1) * BATCH * HID;

        // logits (split-K=2): h @ WaH^T + lpre[t]
        gemm<64, 32, 64, 2, 2, 0, 1><<<dim3(HID / 32, BATCH / 64, 2), 128, SM_S64>>>(
            hr, HID, HID, nullptr, 0, HID, nullptr, 0, 256,
            p_wcvt + OFF_WA, HID + EMB, 0, nullptr,
            p_lpre + (size_t)t * BATCH * HID, 512,
            p_logits2, HID, nullptr, 0);

        attention_kernel<<<BATCH, 256, NP * HID * 2>>>(p_ctx);

        // gates = [ctx, h, xpre_t] @ [W1|Whh|Wih]^T + bg ; fused LSTM
        gemm<64, 64, 64, 2, 2, 1, 0><<<dim3(2048 / 64, BATCH / 64), 128, SM_G64>>>(
            p_ctx, HID, HID, hr, HID, 2 * HID,
            p_xpre + (size_t)t * BATCH * HID, HID, 3 * HID,
            p_Wg3, 3 * HID, 0, nullptr, nullptr, 0,
            nullptr, 0, hw, t);
    }

    // out[b,t,:] = hist @ Wo^T + bo : M=15360, N=96, K=512, permuted write
    gemm<128, 32, 64, 4, 1, 2, 0><<<dim3(NCLS / 32, (TT * BATCH) / 128), 128, SM_O64>>>(
        p_hist, HID, HID, nullptr, 0, HID, nullptr, 0, HID,
        p_wcvt + OFF_WO, HID, 0, bo, nullptr, 0, out, 0, nullptr, 0);
}

// round 13
// speedup vs baseline: 1.0281x; 1.0281x over previous
#include <cuda_runtime.h>
#include <cuda_fp16.h>
#include <math.h>
#include <stdint.h>

#define BATCH 512
#define NP    64
#define CIN   512
#define HID   512
#define EMB   512
#define NCLS  96
#define TT    30

__device__ float  g_featcvt[(size_t)BATCH * NP * CIN];
__device__ __half g_feats_h[(size_t)BATCH * NP * HID];
__device__ float  g_emb[(size_t)TT * BATCH * EMB];
__device__ float  g_pre[(size_t)TT * BATCH * 1024];
__device__ float  g_hist[(size_t)TT * BATCH * HID];
__device__ float  g_hbuf[2][BATCH * HID];
__device__ float  g_c[BATCH * HID];
__device__ float  g_logits2[2][BATCH * HID];
__device__ float  g_ctx[BATCH * HID];
__device__ float  g_x[BATCH * HID];
__device__ float  g_Wg[(size_t)2048 * 1024];
__device__ float  g_bg[2048];
__device__ float  g_Wlx[(size_t)1024 * 512];
__device__ float  g_blx[1024];
#define OFF_WFC 0
#define OFF_WA  (512 * 512)
#define OFF_WC  (OFF_WA + 512 * 1024)
#define OFF_WO  (OFF_WC + 512 * 1024)
#define WCVT_N  (OFF_WO + 96 * 512)
__device__ float g_wcvt[WCVT_N];

__device__ __forceinline__ float f2tf32f(float f) {
    uint32_t r;
    asm("cvt.rna.tf32.f32 %0, %1;" : "=r"(r) : "f"(f));
    return __uint_as_float(r);
}
__device__ __forceinline__ float fsig(float x) {
    return __fdividef(1.f, 1.f + __expf(-x));
}
__device__ __forceinline__ float ftanh(float x) {
    x = fminf(fmaxf(x, -15.f), 15.f);
    float t = __expf(2.f * x);
    return __fdividef(t - 1.f, t + 1.f);
}
__device__ __forceinline__ void cp16(uint32_t dst, const void* src) {
    asm volatile("cp.async.cg.shared.global [%0], [%1], 16;" :: "r"(dst), "l"(src));
}
__device__ __forceinline__ void cp_commit() { asm volatile("cp.async.commit_group;"); }
template <int N>
__device__ __forceinline__ void cp_wait() { asm volatile("cp.async.wait_group %0;" :: "n"(N)); }

template <int BM, int BN, int BK, int S, int WARPS_M, int WARPS_N, int MODE, int SPLITK>
__global__ void __launch_bounds__(WARPS_M * WARPS_N * 32)
gemm(const float* __restrict__ A1, int lda1, int K1,
     const float* __restrict__ A2, int lda2, int K,
     const float* __restrict__ B, int ldb, int boff,
     const float* __restrict__ bias,
     const float* __restrict__ addend, int ldadd,
     void* __restrict__ Cv, int ldc, float* __restrict__ h_out, int t)
{
    constexpr int PAD = 4, ROWF = BK + PAD;
    constexpr int THREADS = WARPS_M * WARPS_N * 32;
    constexpr int WM = BM / WARPS_M, WN = BN / WARPS_N;
    constexpr int M_SUB = WM / 16, N_SUB = WN / 8;
    constexpr int BK4 = BK / 4;
    constexpr int AV = (BM * BK) / (4 * THREADS);
    constexpr int BV = (BN * BK) / (4 * THREADS);
    constexpr int ASTR = BM * ROWF;
    constexpr int BSTR = BN * ROWF;

    if constexpr (SPLITK) {
        if (blockIdx.z) {
            A1 += 256;
            boff += 256;
            Cv = (void*)((float*)Cv + (size_t)BATCH * HID);
            addend = nullptr;
        }
    }

    extern __shared__ float sh[];
    const uint32_t smem_u = (uint32_t)__cvta_generic_to_shared(sh);
    const int bm = blockIdx.y * BM, bn = blockIdx.x * BN;
    const int tid = threadIdx.x;
    const int wid = tid >> 5, lane = tid & 31;
    const int gid = lane >> 2, tig = lane & 3;
    const int warpM = wid % WARPS_M, warpN = wid / WARPS_M;

    float acc[M_SUB][N_SUB][4];
#pragma unroll
    for (int i = 0; i < M_SUB; i++)
#pragma unroll
        for (int j = 0; j < N_SUB; j++)
#pragma unroll
            for (int q = 0; q < 4; q++) acc[i][j][q] = 0.f;

    auto issue = [&](int stg, int k0) {
        const float* Ap; int lda, kc;
        if (k0 < K1) { Ap = A1; lda = lda1; kc = k0; }
        else         { Ap = A2; lda = lda2; kc = k0 - K1; }
        uint32_t ab = smem_u + (uint32_t)(stg * ASTR) * 4u;
#pragma unroll
        for (int i = 0; i < AV; i++) {
            int idx = tid + i * THREADS;
            int r = idx / BK4, c4 = idx % BK4;
            cp16(ab + (uint32_t)(r * ROWF + c4 * 4) * 4u,
                 Ap + (size_t)(bm + r) * lda + kc + c4 * 4);
        }
        uint32_t bb = smem_u + (uint32_t)(S * ASTR + stg * BSTR) * 4u;
#pragma unroll
        for (int i = 0; i < BV; i++) {
            int idx = tid + i * THREADS;
            int r = idx / BK4, c4 = idx % BK4;
            cp16(bb + (uint32_t)(r * ROWF + c4 * 4) * 4u,
                 B + (size_t)(bn + r) * ldb + boff + k0 + c4 * 4);
        }
    };

    const int NK = K / BK;
#pragma unroll
    for (int s = 0; s < S - 1; s++) {
        if (s < NK) issue(s, s * BK);
        cp_commit();
    }

    uint32_t afr[2][M_SUB][4];
    uint32_t bfr[2][N_SUB][2];
    auto ldfrag = [&](const float* As, const float* Bs, int buf, int kb) {
#pragma unroll
        for (int mt = 0; mt < M_SUB; mt++) {
            int r0 = warpM * WM + mt * 16 + gid;
            afr[buf][mt][0] = __float_as_uint(As[r0 * ROWF + kb + tig]);
            afr[buf][mt][1] = __float_as_uint(As[(r0 + 8) * ROWF + kb + tig]);
            afr[buf][mt][2] = __float_as_uint(As[r0 * ROWF + kb + tig + 4]);
            afr[buf][mt][3] = __float_as_uint(As[(r0 + 8) * ROWF + kb + tig + 4]);
        }
#pragma unroll
        for (int nt = 0; nt < N_SUB; nt++) {
            int c0 = warpN * WN + nt * 8 + gid;
            bfr[buf][nt][0] = __float_as_uint(Bs[c0 * ROWF + kb + tig]);
            bfr[buf][nt][1] = __float_as_uint(Bs[c0 * ROWF + kb + tig + 4]);
        }
    };

    for (int k = 0; k < NK; k++) {
        cp_wait<S - 2>();
        __syncthreads();
        int kn = k + S - 1;
        if (kn < NK) issue(kn % S, kn * BK);
        cp_commit();
        const float* As = sh + (k % S) * ASTR;
        const float* Bs = sh + S * ASTR + (k % S) * BSTR;
        ldfrag(As, Bs, 0, 0);
#pragma unroll
        for (int ks = 0; ks < BK / 8; ks++) {
            const int cur = ks & 1, nxt = cur ^ 1;
            if (ks < BK / 8 - 1) ldfrag(As, Bs, nxt, (ks + 1) * 8);
#pragma unroll
            for (int nt = 0; nt < N_SUB; nt++) {
#pragma unroll
                for (int mt = 0; mt < M_SUB; mt++) {
                    asm volatile(
                        "mma.sync.aligned.m16n8k8.row.col.f32.tf32.tf32.f32 "
                        "{%0,%1,%2,%3}, {%4,%5,%6,%7}, {%8,%9}, {%0,%1,%2,%3};"
                        : "+f"(acc[mt][nt][0]), "+f"(acc[mt][nt][1]),
                          "+f"(acc[mt][nt][2]), "+f"(acc[mt][nt][3])
                        : "r"(afr[cur][mt][0]), "r"(afr[cur][mt][1]),
                          "r"(afr[cur][mt][2]), "r"(afr[cur][mt][3]),
                          "r"(bfr[cur][nt][0]), "r"(bfr[cur][nt][1]));
                }
            }
        }
    }

    if constexpr (MODE == 0 || MODE == 5) {
        float* C = (float*)Cv;
#pragma unroll
        for (int mt = 0; mt < M_SUB; mt++) {
#pragma unroll
            for (int nt = 0; nt < N_SUB; nt++) {
                int row0 = bm + warpM * WM + mt * 16 + gid;
                int col  = bn + warpN * WN + nt * 8 + 2 * tig;
                float bx = 0.f, by = 0.f;
                if (bias) { float2 bv = *(const float2*)(bias + col); bx = bv.x; by = bv.y; }
                float a0x = 0.f, a0y = 0.f, a1x = 0.f, a1y = 0.f;
                if (addend) {
                    float2 v = *(const float2*)(addend + (size_t)row0 * ldadd + col);
                    a0x = v.x; a0y = v.y;
                    float2 w = *(const float2*)(addend + (size_t)(row0 + 8) * ldadd + col);
                    a1x = w.x; a1y = w.y;
                }
                float2 v0 = { acc[mt][nt][0] + bx + a0x, acc[mt][nt][1] + by + a0y };
                float2 v1 = { acc[mt][nt][2] + bx + a1x, acc[mt][nt][3] + by + a1y };
                if (MODE == 5) {
                    v0.x = f2tf32f(v0.x); v0.y = f2tf32f(v0.y);
                    v1.x = f2tf32f(v1.x); v1.y = f2tf32f(v1.y);
                }
                *(float2*)(C + (size_t)row0 * ldc + col) = v0;
                *(float2*)(C + (size_t)(row0 + 8) * ldc + col) = v1;
            }
        }
    } else if constexpr (MODE == 4) {
        __half* C = (__half*)Cv;
#pragma unroll
        for (int mt = 0; mt < M_SUB; mt++) {
#pragma unroll
            for (int nt = 0; nt < N_SUB; nt++) {
                int row0 = bm + warpM * WM + mt * 16 + gid;
                int col  = bn + warpN * WN + nt * 8 + 2 * tig;
                float2 bv = *(const float2*)(bias + col);
                *(__half2*)(C + (size_t)row0 * ldc + col) =
                    __floats2half2_rn(acc[mt][nt][0] + bv.x, acc[mt][nt][1] + bv.y);
                *(__half2*)(C + (size_t)(row0 + 8) * ldc + col) =
                    __floats2half2_rn(acc[mt][nt][2] + bv.x, acc[mt][nt][3] + bv.y);
            }
        }
    } else if constexpr (MODE == 2) {
        float* C = (float*)Cv;
#pragma unroll
        for (int mt = 0; mt < M_SUB; mt++) {
#pragma unroll
            for (int nt = 0; nt < N_SUB; nt++) {
                int row0 = bm + warpM * WM + mt * 16 + gid;
                int col  = bn + warpN * WN + nt * 8 + 2 * tig;
                float2 bv = *(const float2*)(bias + col);
#pragma unroll
                for (int rr = 0; rr < 2; rr++) {
                    int r = row0 + rr * 8;
                    int tt = r >> 9, b = r & 511;
                    *(float2*)(C + ((size_t)b * TT + tt) * NCLS + col) =
                        make_float2(acc[mt][nt][rr * 2 + 0] + bv.x,
                                    acc[mt][nt][rr * 2 + 1] + bv.y);
                }
            }
        }
    } else {  // MODE 1: fused LSTM epilogue
        float* Cs = sh;
        constexpr int CPAD = 4;
        __syncthreads();
#pragma unroll
        for (int mt = 0; mt < M_SUB; mt++) {
#pragma unroll
            for (int nt = 0; nt < N_SUB; nt++) {
                int rl = warpM * WM + mt * 16 + gid;
                int cl = warpN * WN + nt * 8 + 2 * tig;
                float b0 = g_bg[bn + cl], b1 = g_bg[bn + cl + 1];
                Cs[rl * (BN + CPAD) + cl]           = acc[mt][nt][0] + b0;
                Cs[rl * (BN + CPAD) + cl + 1]       = acc[mt][nt][1] + b1;
                Cs[(rl + 8) * (BN + CPAD) + cl]     = acc[mt][nt][2] + b0;
                Cs[(rl + 8) * (BN + CPAD) + cl + 1] = acc[mt][nt][3] + b1;
            }
        }
        __syncthreads();
        constexpr int UNITS = BN / 4;
        for (int it = tid; it < BM * UNITS; it += THREADS) {
            int r = it / UNITS, u = it % UNITS;
            float gi = Cs[r * (BN + CPAD) + 4 * u + 0];
            float gf = Cs[r * (BN + CPAD) + 4 * u + 1];
            float gg = Cs[r * (BN + CPAD) + 4 * u + 2];
            float go = Cs[r * (BN + CPAD) + 4 * u + 3];
            int b = bm + r;
            int j = (bn >> 2) + u;
            int idx = b * HID + j;
            float c = g_c[idx];
            float cn = fsig(gf) * c + fsig(gi) * ftanh(gg);
            g_c[idx] = cn;
            float hn = f2tf32f(fsig(go) * ftanh(cn));
            h_out[idx] = hn;
            g_hist[(size_t)t * BATCH * HID + idx] = hn;
        }
    }
}

__global__ void attention_kernel(float* __restrict__ ctx)
{
    extern __shared__ __half sfeat[];
    __shared__ float sa[HID];
    __shared__ float sw[NP];
    __shared__ float red[8];

    const int b = blockIdx.x;
    const int tid = threadIdx.x;
    const int lane = tid & 31, warp = tid >> 5;
    const __half* fb = g_feats_h + (size_t)b * NP * HID;

    {
        uint4* d4 = (uint4*)sfeat;
        const uint4* s4 = (const uint4*)fb;
#pragma unroll
        for (int i = tid; i < NP * HID / 8; i += 256) d4[i] = s4[i];
    }

    const float* l0 = g_logits2[0] + (size_t)b * HID;
    const float* l1 = g_logits2[1] + (size_t)b * HID;
    float v0 = l0[tid] + l1[tid];
    float v1 = l0[tid + 256] + l1[tid + 256];
    float m = fmaxf(v0, v1);
#pragma unroll
    for (int o = 16; o > 0; o >>= 1) m = fmaxf(m, __shfl_xor_sync(~0u, m, o));
    if (lane == 0) red[warp] = m;
    __syncthreads();
    if (tid == 0) {
        float tv = red[0];
#pragma unroll
        for (int i = 1; i < 8; i++) tv = fmaxf(tv, red[i]);
        red[0] = tv;
    }
    __syncthreads();
    m = red[0];
    __syncthreads();
    float e0 = __expf(v0 - m), e1 = __expf(v1 - m);
    float s = e0 + e1;
#pragma unroll
    for (int o = 16; o > 0; o >>= 1) s += __shfl_xor_sync(~0u, s, o);
    if (lane == 0) red[warp] = s;
    __syncthreads();
    if (tid == 0) {
        float tv = 0.f;
#pragma unroll
        for (int i = 0; i < 8; i++) tv += red[i];
        red[0] = tv;
    }
    __syncthreads();
    float inv = __fdividef(1.f, red[0]);
    sa[tid] = e0 * inv;
    sa[tid + 256] = e1 * inv;
    __syncthreads();

    for (int p = warp; p < NP; p += 8) {
        const __half2* fr = (const __half2*)(sfeat + p * HID);
        float sc = 0.f;
#pragma unroll
        for (int e = lane; e < HID / 2; e += 32) {
            float2 f = __half22float2(fr[e]);
            float2 a = *(const float2*)(sa + 2 * e);
            sc += f.x * a.x + f.y * a.y;
        }
#pragma unroll
        for (int o = 16; o > 0; o >>= 1) sc += __shfl_xor_sync(~0u, sc, o);
        if (lane == 0) sw[p] = sc;
    }
    __syncthreads();

    if (tid < 32) {
        float w0 = sw[tid], w1 = sw[tid + 32];
        float mm = fmaxf(w0, w1);
#pragma unroll
        for (int o = 16; o > 0; o >>= 1) mm = fmaxf(mm, __shfl_xor_sync(~0u, mm, o));
        float f0 = __expf(w0 - mm), f1 = __expf(w1 - mm);
        float ss = f0 + f1;
#pragma unroll
        for (int o = 16; o > 0; o >>= 1) ss += __shfl_xor_sync(~0u, ss, o);
        float iv = __fdividef(1.f, ss);
        sw[tid] = f0 * iv;
        sw[tid + 32] = f1 * iv;
    }
    __syncthreads();

    float2 a2 = {0.f, 0.f};
#pragma unroll 8
    for (int p = 0; p < NP; p++) {
        float w = sw[p];
        float2 f = __half22float2(*(const __half2*)(sfeat + p * HID + 2 * tid));
        a2.x += w * f.x;
        a2.y += w * f.y;
    }
    *(float2*)(ctx + (size_t)b * HID + 2 * tid) =
        make_float2(f2tf32f(a2.x), f2tf32f(a2.y));
}

__global__ void zero_hc_kernel()
{
    int idx = blockIdx.x * blockDim.x + threadIdx.x;
    g_hbuf[0][idx] = 0.f;
    g_c[idx] = 0.f;
}

__global__ void cvt_copy_kernel(const float* __restrict__ src, float* __restrict__ dst, int n4)
{
    for (int i = blockIdx.x * blockDim.x + threadIdx.x; i < n4; i += gridDim.x * blockDim.x) {
        float4 v = ((const float4*)src)[i];
        v.x = f2tf32f(v.x); v.y = f2tf32f(v.y);
        v.z = f2tf32f(v.z); v.w = f2tf32f(v.w);
        ((float4*)dst)[i] = v;
    }
}

__global__ void cvt_weights_kernel(const float* __restrict__ Wfc, const float* __restrict__ Wa,
                                   const float* __restrict__ Wc, const float* __restrict__ Wo)
{
    const int n4 = WCVT_N / 4;
    for (int i = blockIdx.x * blockDim.x + threadIdx.x; i < n4; i += gridDim.x * blockDim.x) {
        int e = i * 4;
        const float* src;
        if (e < OFF_WA)      src = Wfc + e;
        else if (e < OFF_WC) src = Wa + (e - OFF_WA);
        else if (e < OFF_WO) src = Wc + (e - OFF_WC);
        else                 src = Wo + (e - OFF_WO);
        float4 v = *(const float4*)src;
        v.x = f2tf32f(v.x); v.y = f2tf32f(v.y);
        v.z = f2tf32f(v.z); v.w = f2tf32f(v.w);
        *(float4*)(g_wcvt + e) = v;
    }
}

__global__ void build_wg_kernel(const float* __restrict__ Wih, const float* __restrict__ Whh,
                                const float* __restrict__ bih, const float* __restrict__ bhh)
{
    int idx = blockIdx.x * blockDim.x + threadIdx.x;
    int rn = idx >> 10, k = idx & 1023;
    int j = rn >> 2, gi = rn & 3;
    int orig = gi * 512 + j;
    float v = (k < 512) ? Wih[(size_t)orig * 512 + k] : Whh[(size_t)orig * 512 + (k - 512)];
    g_Wg[idx] = f2tf32f(v);
    if (k == 0) g_bg[rn] = bih[orig] + bhh[orig];
}

__global__ void build_wlx_kernel(const float* __restrict__ Wa, const float* __restrict__ Wc,
                                 const float* __restrict__ ba, const float* __restrict__ bc)
{
    int idx = blockIdx.x * blockDim.x + threadIdx.x;
    int rn = idx >> 9, k = idx & 511;
    float v = (rn < 512) ? Wa[(size_t)rn * 1024 + 512 + k]
                         : Wc[(size_t)(rn - 512) * 1024 + k];
    g_Wlx[idx] = f2tf32f(v);
    if (k == 0) g_blx[rn] = (rn < 512) ? ba[rn] : bc[rn - 512];
}

__global__ void gather_emb_kernel(const int* __restrict__ targets,
                                  const float* __restrict__ table)
{
    int b = blockIdx.x;
    int t = blockIdx.y;
    int id = (t == 0) ? 0 : targets[(size_t)b * TT + (t - 1)];
    const float4* src = (const float4*)(table + (size_t)id * EMB);
    float4* dst = (float4*)(g_emb + ((size_t)t * BATCH + b) * EMB);
    int e = threadIdx.x;
    float4 v = src[e];
    v.x = f2tf32f(v.x); v.y = f2tf32f(v.y);
    v.z = f2tf32f(v.z); v.w = f2tf32f(v.w);
    dst[e] = v;
}

extern "C" void kernel_launch(void* const* d_in, const int* in_sizes, int n_in,
                              void* d_out, int out_size)
{
    const float* features  = (const float*)d_in[0];
    const int*   targets   = (const int*)d_in[1];
    const float* Wfc = (const float*)d_in[3];
    const float* bfc = (const float*)d_in[4];
    const float* emb_table = (const float*)d_in[5];
    const float* Wa  = (const float*)d_in[6];
    const float* ba  = (const float*)d_in[7];
    const float* Wc  = (const float*)d_in[8];
    const float* bc  = (const float*)d_in[9];
    const float* Wih = (const float*)d_in[10];
    const float* Whh = (const float*)d_in[11];
    const float* bih = (const float*)d_in[12];
    const float* bhh = (const float*)d_in[13];
    const float* Wo  = (const float*)d_in[14];
    const float* bo  = (const float*)d_in[15];
    float* out = (float*)d_out;

    float *p_featcvt, *p_emb, *p_pre, *p_hist, *p_hbuf, *p_logits2, *p_ctx, *p_x;
    float *p_Wg, *p_Wlx, *p_blx, *p_wcvt;
    __half* p_feats_h;
    cudaGetSymbolAddress((void**)&p_featcvt, g_featcvt);
    cudaGetSymbolAddress((void**)&p_feats_h, g_feats_h);
    cudaGetSymbolAddress((void**)&p_emb,     g_emb);
    cudaGetSymbolAddress((void**)&p_pre,     g_pre);
    cudaGetSymbolAddress((void**)&p_hist,    g_hist);
    cudaGetSymbolAddress((void**)&p_hbuf,    g_hbuf);
    cudaGetSymbolAddress((void**)&p_logits2, g_logits2);
    cudaGetSymbolAddress((void**)&p_ctx,     g_ctx);
    cudaGetSymbolAddress((void**)&p_x,       g_x);
    cudaGetSymbolAddress((void**)&p_Wg,      g_Wg);
    cudaGetSymbolAddress((void**)&p_Wlx,     g_Wlx);
    cudaGetSymbolAddress((void**)&p_blx,     g_blx);
    cudaGetSymbolAddress((void**)&p_wcvt,    g_wcvt);

    constexpr int SM_BIG32 = 3 * (128 + 64) * 36 * 4;   // 82944
    constexpr int SM_G64   = 3 * (128 + 64) * 68 * 4;   // 156672
    constexpr int SM_L128  = 2 * (64 + 32) * 132 * 4;   // 101376
    constexpr int SM_O64   = 3 * (128 + 32) * 68 * 4;   // 130560

    cudaFuncSetAttribute((const void*)gemm<128, 64, 32, 3, 4, 2, 4, 0>,
                         cudaFuncAttributeMaxDynamicSharedMemorySize, SM_BIG32);
    cudaFuncSetAttribute((const void*)gemm<128, 64, 32, 3, 4, 2, 0, 0>,
                         cudaFuncAttributeMaxDynamicSharedMemorySize, SM_BIG32);
    cudaFuncSetAttribute((const void*)gemm<64, 32, 128, 2, 2, 2, 0, 1>,
                         cudaFuncAttributeMaxDynamicSharedMemorySize, SM_L128);
    cudaFuncSetAttribute((const void*)gemm<64, 32, 128, 2, 2, 2, 5, 0>,
                         cudaFuncAttributeMaxDynamicSharedMemorySize, SM_L128);
    cudaFuncSetAttribute((const void*)gemm<128, 64, 64, 3, 4, 2, 1, 0>,
                         cudaFuncAttributeMaxDynamicSharedMemorySize, SM_G64);
    cudaFuncSetAttribute((const void*)gemm<128, 32, 64, 3, 4, 1, 2, 0>,
                         cudaFuncAttributeMaxDynamicSharedMemorySize, SM_O64);
    cudaFuncSetAttribute((const void*)attention_kernel,
                         cudaFuncAttributeMaxDynamicSharedMemorySize, NP * HID * 2);

    zero_hc_kernel<<<(BATCH * HID) / 256, 256>>>();
    build_wg_kernel<<<(2048 * 1024) / 256, 256>>>(Wih, Whh, bih, bhh);
    build_wlx_kernel<<<(1024 * 512) / 256, 256>>>(Wa, Wc, ba, bc);
    gather_emb_kernel<<<dim3(BATCH, TT), 128>>>(targets, emb_table);
    cvt_weights_kernel<<<592, 256>>>(Wfc, Wa, Wc, Wo);
    cvt_copy_kernel<<<1024, 256>>>(features, p_featcvt, BATCH * NP * CIN / 4);

    gemm<128, 64, 32, 3, 4, 2, 4, 0><<<dim3(HID / 64, (BATCH * NP) / 128), 256, SM_BIG32>>>(
        p_featcvt, CIN, CIN, nullptr, 0, CIN,
        p_wcvt + OFF_WFC, CIN, 0, bfc, nullptr, 0, p_feats_h, HID, nullptr, 0);

    gemm<128, 64, 32, 3, 4, 2, 0, 0><<<dim3(1024 / 64, (TT * BATCH) / 128), 256, SM_BIG32>>>(
        p_emb, EMB, EMB, nullptr, 0, EMB,
        p_Wlx, 512, 0, p_blx, nullptr, 0, p_pre, 1024, nullptr, 0);

    for (int t = 0; t < TT; t++) {
        float* hr = p_hbuf + (t & 1) * BATCH * HID;
        float* hw = p_hbuf + ((t + 1) & 1) * BATCH * HID;
        const float* pre_t = p_pre + (size_t)t * BATCH * 1024;

        gemm<64, 32, 128, 2, 2, 2, 0, 1><<<dim3(HID / 32, BATCH / 64, 2), 128, SM_L128>>>(
            hr, HID, HID, nullptr, 0, 256,
            p_wcvt + OFF_WA, HID + EMB, 0, nullptr, pre_t, 1024,
            p_logits2, HID, nullptr, 0);

        attention_kernel<<<BATCH, 256, NP * HID * 2>>>(p_ctx);

        gemm<64, 32, 128, 2, 2, 2, 5, 0><<<dim3(HID / 32, BATCH / 64), 128, SM_L128>>>(
            p_ctx, HID, HID, nullptr, 0, HID,
            p_wcvt + OFF_WC, EMB + HID, 512, nullptr, pre_t + 512, 1024,
            p_x, HID, nullptr, 0);

        gemm<128, 64, 64, 3, 4, 2, 1, 0><<<dim3((4 * HID) / 64, BATCH / 128), 256, SM_G64>>>(
            p_x, HID, HID, hr, HID, 2 * HID,
            p_Wg, 2 * HID, 0, nullptr, nullptr, 0, nullptr, 0, hw, t);
    }

    gemm<128, 32, 64, 3, 4, 1, 2, 0><<<dim3(NCLS / 32, (TT * BATCH) / 128), 128, SM_O64>>>(
        p_hist, HID, HID, nullptr, 0, HID,
        p_wcvt + OFF_WO, HID, 0, bo, nullptr, 0, out, 0, nullptr, 0);
}

// round 14
// speedup vs baseline: 1.0715x; 1.0422x over previous
#include <cuda_runtime.h>
#include <cuda_fp16.h>
#include <math.h>
#include <stdint.h>

#define BATCH 512
#define NP    64
#define CIN   512
#define HID   512
#define EMB   512
#define NCLS  96
#define TT    30

__device__ float  g_featcvt[(size_t)BATCH * NP * CIN];
__device__ __half g_feats_h[(size_t)BATCH * NP * HID];
__device__ float  g_emb[(size_t)TT * BATCH * EMB];
__device__ float  g_pre[(size_t)TT * BATCH * 1024];
__device__ float  g_hist[(size_t)TT * BATCH * HID];
__device__ float  g_hbuf[2][BATCH * HID];
__device__ float  g_c[BATCH * HID];
__device__ float  g_logits2[2][BATCH * HID];
__device__ float  g_ctx[BATCH * HID];
__device__ float  g_x[BATCH * HID];
__device__ float  g_Wg[(size_t)2048 * 1024];
__device__ float  g_bg[2048];
__device__ float  g_Wlx[(size_t)1024 * 512];
__device__ float  g_blx[1024];
#define OFF_WFC 0
#define OFF_WA  (512 * 512)
#define OFF_WC  (OFF_WA + 512 * 1024)
#define OFF_WO  (OFF_WC + 512 * 1024)
#define WCVT_N  (OFF_WO + 96 * 512)
__device__ float g_wcvt[WCVT_N];

__device__ __forceinline__ float f2tf32f(float f) {
    uint32_t r;
    asm("cvt.rna.tf32.f32 %0, %1;" : "=r"(r) : "f"(f));
    return __uint_as_float(r);
}
__device__ __forceinline__ float fsig(float x) {
    return __fdividef(1.f, 1.f + __expf(-x));
}
__device__ __forceinline__ float ftanh(float x) {
    x = fminf(fmaxf(x, -15.f), 15.f);
    float t = __expf(2.f * x);
    return __fdividef(t - 1.f, t + 1.f);
}
__device__ __forceinline__ void cp16(uint32_t dst, const void* src) {
    asm volatile("cp.async.cg.shared.global [%0], [%1], 16;" :: "r"(dst), "l"(src));
}
__device__ __forceinline__ void cp_commit() { asm volatile("cp.async.commit_group;"); }
template <int N>
__device__ __forceinline__ void cp_wait() { asm volatile("cp.async.wait_group %0;" :: "n"(N)); }

// ------------- TF32 GEMM, cp.async 3-stage + frag double-buffer -----------
// MODE 0: float C = acc (+bias)(+addend[ldadd])
// MODE 1: fused LSTM epilogue
// MODE 2: permuted fp32 out-projection write
// MODE 4: half C = acc + bias
// MODE 5: tf32-rounded float C = acc (+bias)(+addend)
// SPLITK: blockIdx.z selects K-half (K passed as 256).
template <int BM, int BN, int BK, int WARPS_M, int WARPS_N, int MODE, int SPLITK>
__global__ void __launch_bounds__(WARPS_M * WARPS_N * 32)
gemm(const float* __restrict__ A1, int lda1, int K1,
     const float* __restrict__ A2, int lda2, int K,
     const float* __restrict__ B, int ldb, int boff,
     const float* __restrict__ bias,
     const float* __restrict__ addend, int ldadd,
     void* __restrict__ Cv, int ldc, float* __restrict__ h_out, int t)
{
    constexpr int S = 3, PAD = 4, ROWF = BK + PAD;
    constexpr int THREADS = WARPS_M * WARPS_N * 32;
    constexpr int WM = BM / WARPS_M, WN = BN / WARPS_N;
    constexpr int M_SUB = WM / 16, N_SUB = WN / 8;
    constexpr int BK4 = BK / 4;
    constexpr int AV = (BM * BK) / (4 * THREADS);
    constexpr int BV = (BN * BK) / (4 * THREADS);
    constexpr int ASTR = BM * ROWF;
    constexpr int BSTR = BN * ROWF;

    if constexpr (SPLITK) {
        if (blockIdx.z) {
            A1 += 256;
            boff += 256;
            Cv = (void*)((float*)Cv + (size_t)BATCH * HID);
            addend = nullptr;
        }
    }

    extern __shared__ float sh[];
    const uint32_t smem_u = (uint32_t)__cvta_generic_to_shared(sh);
    const int bm = blockIdx.y * BM, bn = blockIdx.x * BN;
    const int tid = threadIdx.x;
    const int wid = tid >> 5, lane = tid & 31;
    const int gid = lane >> 2, tig = lane & 3;
    const int warpM = wid % WARPS_M, warpN = wid / WARPS_M;

    float acc[M_SUB][N_SUB][4];
#pragma unroll
    for (int i = 0; i < M_SUB; i++)
#pragma unroll
        for (int j = 0; j < N_SUB; j++)
#pragma unroll
            for (int q = 0; q < 4; q++) acc[i][j][q] = 0.f;

    auto issue = [&](int stg, int k0) {
        const float* Ap; int lda, kc;
        if (k0 < K1) { Ap = A1; lda = lda1; kc = k0; }
        else         { Ap = A2; lda = lda2; kc = k0 - K1; }
        uint32_t ab = smem_u + (uint32_t)(stg * ASTR) * 4u;
#pragma unroll
        for (int i = 0; i < AV; i++) {
            int idx = tid + i * THREADS;
            int r = idx / BK4, c4 = idx % BK4;
            cp16(ab + (uint32_t)(r * ROWF + c4 * 4) * 4u,
                 Ap + (size_t)(bm + r) * lda + kc + c4 * 4);
        }
        uint32_t bb = smem_u + (uint32_t)(S * ASTR + stg * BSTR) * 4u;
#pragma unroll
        for (int i = 0; i < BV; i++) {
            int idx = tid + i * THREADS;
            int r = idx / BK4, c4 = idx % BK4;
            cp16(bb + (uint32_t)(r * ROWF + c4 * 4) * 4u,
                 B + (size_t)(bn + r) * ldb + boff + k0 + c4 * 4);
        }
    };

    const int NK = K / BK;
    issue(0, 0);  cp_commit();
    issue(1, BK); cp_commit();

    uint32_t afr[2][M_SUB][4];
    uint32_t bfr[2][N_SUB][2];
    auto ldfrag = [&](const float* As, const float* Bs, int buf, int kb) {
#pragma unroll
        for (int mt = 0; mt < M_SUB; mt++) {
            int r0 = warpM * WM + mt * 16 + gid;
            afr[buf][mt][0] = __float_as_uint(As[r0 * ROWF + kb + tig]);
            afr[buf][mt][1] = __float_as_uint(As[(r0 + 8) * ROWF + kb + tig]);
            afr[buf][mt][2] = __float_as_uint(As[r0 * ROWF + kb + tig + 4]);
            afr[buf][mt][3] = __float_as_uint(As[(r0 + 8) * ROWF + kb + tig + 4]);
        }
#pragma unroll
        for (int nt = 0; nt < N_SUB; nt++) {
            int c0 = warpN * WN + nt * 8 + gid;
            bfr[buf][nt][0] = __float_as_uint(Bs[c0 * ROWF + kb + tig]);
            bfr[buf][nt][1] = __float_as_uint(Bs[c0 * ROWF + kb + tig + 4]);
        }
    };

    for (int k = 0; k < NK; k++) {
        cp_wait<1>();
        __syncthreads();
        int kn = k + S - 1;
        if (kn < NK) issue(kn % S, kn * BK);
        cp_commit();
        const float* As = sh + (k % S) * ASTR;
        const float* Bs = sh + S * ASTR + (k % S) * BSTR;
        ldfrag(As, Bs, 0, 0);
#pragma unroll
        for (int ks = 0; ks < BK / 8; ks++) {
            const int cur = ks & 1, nxt = cur ^ 1;
            if (ks < BK / 8 - 1) ldfrag(As, Bs, nxt, (ks + 1) * 8);
#pragma unroll
            for (int nt = 0; nt < N_SUB; nt++) {
#pragma unroll
                for (int mt = 0; mt < M_SUB; mt++) {
                    asm volatile(
                        "mma.sync.aligned.m16n8k8.row.col.f32.tf32.tf32.f32 "
                        "{%0,%1,%2,%3}, {%4,%5,%6,%7}, {%8,%9}, {%0,%1,%2,%3};"
                        : "+f"(acc[mt][nt][0]), "+f"(acc[mt][nt][1]),
                          "+f"(acc[mt][nt][2]), "+f"(acc[mt][nt][3])
                        : "r"(afr[cur][mt][0]), "r"(afr[cur][mt][1]),
                          "r"(afr[cur][mt][2]), "r"(afr[cur][mt][3]),
                          "r"(bfr[cur][nt][0]), "r"(bfr[cur][nt][1]));
                }
            }
        }
    }

    if constexpr (MODE == 0 || MODE == 5) {
        float* C = (float*)Cv;
#pragma unroll
        for (int mt = 0; mt < M_SUB; mt++) {
#pragma unroll
            for (int nt = 0; nt < N_SUB; nt++) {
                int row0 = bm + warpM * WM + mt * 16 + gid;
                int col  = bn + warpN * WN + nt * 8 + 2 * tig;
                float bx = 0.f, by = 0.f;
                if (bias) { float2 bv = *(const float2*)(bias + col); bx = bv.x; by = bv.y; }
                float a0x = 0.f, a0y = 0.f, a1x = 0.f, a1y = 0.f;
                if (addend) {
                    float2 v = *(const float2*)(addend + (size_t)row0 * ldadd + col);
                    a0x = v.x; a0y = v.y;
                    float2 w = *(const float2*)(addend + (size_t)(row0 + 8) * ldadd + col);
                    a1x = w.x; a1y = w.y;
                }
                float2 v0 = { acc[mt][nt][0] + bx + a0x, acc[mt][nt][1] + by + a0y };
                float2 v1 = { acc[mt][nt][2] + bx + a1x, acc[mt][nt][3] + by + a1y };
                if (MODE == 5) {
                    v0.x = f2tf32f(v0.x); v0.y = f2tf32f(v0.y);
                    v1.x = f2tf32f(v1.x); v1.y = f2tf32f(v1.y);
                }
                *(float2*)(C + (size_t)row0 * ldc + col) = v0;
                *(float2*)(C + (size_t)(row0 + 8) * ldc + col) = v1;
            }
        }
    } else if constexpr (MODE == 4) {
        __half* C = (__half*)Cv;
#pragma unroll
        for (int mt = 0; mt < M_SUB; mt++) {
#pragma unroll
            for (int nt = 0; nt < N_SUB; nt++) {
                int row0 = bm + warpM * WM + mt * 16 + gid;
                int col  = bn + warpN * WN + nt * 8 + 2 * tig;
                float2 bv = *(const float2*)(bias + col);
                *(__half2*)(C + (size_t)row0 * ldc + col) =
                    __floats2half2_rn(acc[mt][nt][0] + bv.x, acc[mt][nt][1] + bv.y);
                *(__half2*)(C + (size_t)(row0 + 8) * ldc + col) =
                    __floats2half2_rn(acc[mt][nt][2] + bv.x, acc[mt][nt][3] + bv.y);
            }
        }
    } else if constexpr (MODE == 2) {
        float* C = (float*)Cv;
#pragma unroll
        for (int mt = 0; mt < M_SUB; mt++) {
#pragma unroll
            for (int nt = 0; nt < N_SUB; nt++) {
                int row0 = bm + warpM * WM + mt * 16 + gid;
                int col  = bn + warpN * WN + nt * 8 + 2 * tig;
                float2 bv = *(const float2*)(bias + col);
#pragma unroll
                for (int rr = 0; rr < 2; rr++) {
                    int r = row0 + rr * 8;
                    int tt = r >> 9, b = r & 511;
                    *(float2*)(C + ((size_t)b * TT + tt) * NCLS + col) =
                        make_float2(acc[mt][nt][rr * 2 + 0] + bv.x,
                                    acc[mt][nt][rr * 2 + 1] + bv.y);
                }
            }
        }
    } else {  // MODE 1: fused LSTM epilogue
        float* Cs = sh;
        constexpr int CPAD = 4;
        __syncthreads();
#pragma unroll
        for (int mt = 0; mt < M_SUB; mt++) {
#pragma unroll
            for (int nt = 0; nt < N_SUB; nt++) {
                int rl = warpM * WM + mt * 16 + gid;
                int cl = warpN * WN + nt * 8 + 2 * tig;
                float b0 = g_bg[bn + cl], b1 = g_bg[bn + cl + 1];
                Cs[rl * (BN + CPAD) + cl]           = acc[mt][nt][0] + b0;
                Cs[rl * (BN + CPAD) + cl + 1]       = acc[mt][nt][1] + b1;
                Cs[(rl + 8) * (BN + CPAD) + cl]     = acc[mt][nt][2] + b0;
                Cs[(rl + 8) * (BN + CPAD) + cl + 1] = acc[mt][nt][3] + b1;
            }
        }
        __syncthreads();
        constexpr int UNITS = BN / 4;
        for (int it = tid; it < BM * UNITS; it += THREADS) {
            int r = it / UNITS, u = it % UNITS;
            float gi = Cs[r * (BN + CPAD) + 4 * u + 0];
            float gf = Cs[r * (BN + CPAD) + 4 * u + 1];
            float gg = Cs[r * (BN + CPAD) + 4 * u + 2];
            float go = Cs[r * (BN + CPAD) + 4 * u + 3];
            int b = bm + r;
            int j = (bn >> 2) + u;
            int idx = b * HID + j;
            float c = g_c[idx];
            float cn = fsig(gf) * c + fsig(gi) * ftanh(gg);
            g_c[idx] = cn;
            float hn = f2tf32f(fsig(go) * ftanh(cn));
            h_out[idx] = hn;
            g_hist[(size_t)t * BATCH * HID + idx] = hn;
        }
    }
}

// ---- fused attention: smem-staged fp16 feats, read once -------------------
__global__ void attention_kernel(float* __restrict__ ctx)
{
    extern __shared__ __half sfeat[];
    __shared__ float sa[HID];
    __shared__ float sw[NP];
    __shared__ float red[8];

    const int b = blockIdx.x;
    const int tid = threadIdx.x;
    const int lane = tid & 31, warp = tid >> 5;
    const __half* fb = g_feats_h + (size_t)b * NP * HID;

    {
        uint4* d4 = (uint4*)sfeat;
        const uint4* s4 = (const uint4*)fb;
#pragma unroll
        for (int i = tid; i < NP * HID / 8; i += 256) d4[i] = s4[i];
    }

    const float* l0 = g_logits2[0] + (size_t)b * HID;
    const float* l1 = g_logits2[1] + (size_t)b * HID;
    float v0 = l0[tid] + l1[tid];
    float v1 = l0[tid + 256] + l1[tid + 256];
    float m = fmaxf(v0, v1);
#pragma unroll
    for (int o = 16; o > 0; o >>= 1) m = fmaxf(m, __shfl_xor_sync(~0u, m, o));
    if (lane == 0) red[warp] = m;
    __syncthreads();
    if (tid == 0) {
        float tv = red[0];
#pragma unroll
        for (int i = 1; i < 8; i++) tv = fmaxf(tv, red[i]);
        red[0] = tv;
    }
    __syncthreads();
    m = red[0];
    __syncthreads();
    float e0 = __expf(v0 - m), e1 = __expf(v1 - m);
    float s = e0 + e1;
#pragma unroll
    for (int o = 16; o > 0; o >>= 1) s += __shfl_xor_sync(~0u, s, o);
    if (lane == 0) red[warp] = s;
    __syncthreads();
    if (tid == 0) {
        float tv = 0.f;
#pragma unroll
        for (int i = 0; i < 8; i++) tv += red[i];
        red[0] = tv;
    }
    __syncthreads();
    float inv = __fdividef(1.f, red[0]);
    sa[tid] = e0 * inv;
    sa[tid + 256] = e1 * inv;
    __syncthreads();

    for (int p = warp; p < NP; p += 8) {
        const __half2* fr = (const __half2*)(sfeat + p * HID);
        float sc = 0.f;
#pragma unroll
        for (int e = lane; e < HID / 2; e += 32) {
            float2 f = __half22float2(fr[e]);
            float2 a = *(const float2*)(sa + 2 * e);
            sc += f.x * a.x + f.y * a.y;
        }
#pragma unroll
        for (int o = 16; o > 0; o >>= 1) sc += __shfl_xor_sync(~0u, sc, o);
        if (lane == 0) sw[p] = sc;
    }
    __syncthreads();

    if (tid < 32) {
        float w0 = sw[tid], w1 = sw[tid + 32];
        float mm = fmaxf(w0, w1);
#pragma unroll
        for (int o = 16; o > 0; o >>= 1) mm = fmaxf(mm, __shfl_xor_sync(~0u, mm, o));
        float f0 = __expf(w0 - mm), f1 = __expf(w1 - mm);
        float ss = f0 + f1;
#pragma unroll
        for (int o = 16; o > 0; o >>= 1) ss += __shfl_xor_sync(~0u, ss, o);
        float iv = __fdividef(1.f, ss);
        sw[tid] = f0 * iv;
        sw[tid + 32] = f1 * iv;
    }
    __syncthreads();

    float2 a2 = {0.f, 0.f};
#pragma unroll 8
    for (int p = 0; p < NP; p++) {
        float w = sw[p];
        float2 f = __half22float2(*(const __half2*)(sfeat + p * HID + 2 * tid));
        a2.x += w * f.x;
        a2.y += w * f.y;
    }
    *(float2*)(ctx + (size_t)b * HID + 2 * tid) =
        make_float2(f2tf32f(a2.x), f2tf32f(a2.y));
}

// ---------------- setup kernels -------------------------------------------
__global__ void zero_hc_kernel()
{
    int idx = blockIdx.x * blockDim.x + threadIdx.x;
    g_hbuf[0][idx] = 0.f;
    g_c[idx] = 0.f;
}

__global__ void cvt_copy_kernel(const float* __restrict__ src, float* __restrict__ dst, int n4)
{
    for (int i = blockIdx.x * blockDim.x + threadIdx.x; i < n4; i += gridDim.x * blockDim.x) {
        float4 v = ((const float4*)src)[i];
        v.x = f2tf32f(v.x); v.y = f2tf32f(v.y);
        v.z = f2tf32f(v.z); v.w = f2tf32f(v.w);
        ((float4*)dst)[i] = v;
    }
}

// fused weight conversion into g_wcvt (all four regions, one launch)
__global__ void cvt_weights_kernel(const float* __restrict__ Wfc, const float* __restrict__ Wa,
                                   const float* __restrict__ Wc, const float* __restrict__ Wo)
{
    const int n4 = WCVT_N / 4;
    for (int i = blockIdx.x * blockDim.x + threadIdx.x; i < n4; i += gridDim.x * blockDim.x) {
        int e = i * 4;
        const float* src;
        if (e < OFF_WA)      src = Wfc + e;
        else if (e < OFF_WC) src = Wa + (e - OFF_WA);
        else if (e < OFF_WO) src = Wc + (e - OFF_WC);
        else                 src = Wo + (e - OFF_WO);
        float4 v = *(const float4*)src;
        v.x = f2tf32f(v.x); v.y = f2tf32f(v.y);
        v.z = f2tf32f(v.z); v.w = f2tf32f(v.w);
        *(float4*)(g_wcvt + e) = v;
    }
}

__global__ void build_wg_kernel(const float* __restrict__ Wih, const float* __restrict__ Whh,
                                const float* __restrict__ bih, const float* __restrict__ bhh)
{
    int idx = blockIdx.x * blockDim.x + threadIdx.x;
    int rn = idx >> 10, k = idx & 1023;
    int j = rn >> 2, gi = rn & 3;
    int orig = gi * 512 + j;
    float v = (k < 512) ? Wih[(size_t)orig * 512 + k] : Whh[(size_t)orig * 512 + (k - 512)];
    g_Wg[idx] = f2tf32f(v);
    if (k == 0) g_bg[rn] = bih[orig] + bhh[orig];
}

__global__ void build_wlx_kernel(const float* __restrict__ Wa, const float* __restrict__ Wc,
                                 const float* __restrict__ ba, const float* __restrict__ bc)
{
    int idx = blockIdx.x * blockDim.x + threadIdx.x;
    int rn = idx >> 9, k = idx & 511;
    float v = (rn < 512) ? Wa[(size_t)rn * 1024 + 512 + k]
                         : Wc[(size_t)(rn - 512) * 1024 + k];
    g_Wlx[idx] = f2tf32f(v);
    if (k == 0) g_blx[rn] = (rn < 512) ? ba[rn] : bc[rn - 512];
}

__global__ void gather_emb_kernel(const int* __restrict__ targets,
                                  const float* __restrict__ table)
{
    int b = blockIdx.x;
    int t = blockIdx.y;
    int id = (t == 0) ? 0 : targets[(size_t)b * TT + (t - 1)];
    const float4* src = (const float4*)(table + (size_t)id * EMB);
    float4* dst = (float4*)(g_emb + ((size_t)t * BATCH + b) * EMB);
    int e = threadIdx.x;
    float4 v = src[e];
    v.x = f2tf32f(v.x); v.y = f2tf32f(v.y);
    v.z = f2tf32f(v.z); v.w = f2tf32f(v.w);
    dst[e] = v;
}

// ---------------- launch ----------------------------------------------------
extern "C" void kernel_launch(void* const* d_in, const int* in_sizes, int n_in,
                              void* d_out, int out_size)
{
    const float* features  = (const float*)d_in[0];
    const int*   targets   = (const int*)d_in[1];
    const float* Wfc = (const float*)d_in[3];
    const float* bfc = (const float*)d_in[4];
    const float* emb_table = (const float*)d_in[5];
    const float* Wa  = (const float*)d_in[6];
    const float* ba  = (const float*)d_in[7];
    const float* Wc  = (const float*)d_in[8];
    const float* bc  = (const float*)d_in[9];
    const float* Wih = (const float*)d_in[10];
    const float* Whh = (const float*)d_in[11];
    const float* bih = (const float*)d_in[12];
    const float* bhh = (const float*)d_in[13];
    const float* Wo  = (const float*)d_in[14];
    const float* bo  = (const float*)d_in[15];
    float* out = (float*)d_out;

    float *p_featcvt, *p_emb, *p_pre, *p_hist, *p_hbuf, *p_logits2, *p_ctx, *p_x;
    float *p_Wg, *p_Wlx, *p_blx, *p_wcvt;
    __half* p_feats_h;
    cudaGetSymbolAddress((void**)&p_featcvt, g_featcvt);
    cudaGetSymbolAddress((void**)&p_feats_h, g_feats_h);
    cudaGetSymbolAddress((void**)&p_emb,     g_emb);
    cudaGetSymbolAddress((void**)&p_pre,     g_pre);
    cudaGetSymbolAddress((void**)&p_hist,    g_hist);
    cudaGetSymbolAddress((void**)&p_hbuf,    g_hbuf);
    cudaGetSymbolAddress((void**)&p_logits2, g_logits2);
    cudaGetSymbolAddress((void**)&p_ctx,     g_ctx);
    cudaGetSymbolAddress((void**)&p_x,       g_x);
    cudaGetSymbolAddress((void**)&p_Wg,      g_Wg);
    cudaGetSymbolAddress((void**)&p_Wlx,     g_Wlx);
    cudaGetSymbolAddress((void**)&p_blx,     g_blx);
    cudaGetSymbolAddress((void**)&p_wcvt,    g_wcvt);

    constexpr int SM_BIG32 = 3 * (128 + 64) * 36 * 4;   // 82944  (BK=32, S=3)
    constexpr int SM_G64   = 3 * (64 + 64) * 68 * 4;    // 104448 (BK=64, gates 64x64)
    constexpr int SM_S64   = 3 * (64 + 32) * 68 * 4;    // 78336  (BK=64)
    constexpr int SM_O64   = 3 * (128 + 32) * 68 * 4;   // 130560 (BK=64)

    cudaFuncSetAttribute((const void*)gemm<128, 64, 32, 4, 2, 4, 0>,
                         cudaFuncAttributeMaxDynamicSharedMemorySize, SM_BIG32);
    cudaFuncSetAttribute((const void*)gemm<128, 64, 32, 4, 2, 0, 0>,
                         cudaFuncAttributeMaxDynamicSharedMemorySize, SM_BIG32);
    cudaFuncSetAttribute((const void*)gemm<64, 32, 64, 2, 2, 0, 1>,
                         cudaFuncAttributeMaxDynamicSharedMemorySize, SM_S64);
    cudaFuncSetAttribute((const void*)gemm<64, 32, 64, 2, 2, 5, 0>,
                         cudaFuncAttributeMaxDynamicSharedMemorySize, SM_S64);
    cudaFuncSetAttribute((const void*)gemm<64, 64, 64, 2, 2, 1, 0>,
                         cudaFuncAttributeMaxDynamicSharedMemorySize, SM_G64);
    cudaFuncSetAttribute((const void*)gemm<128, 32, 64, 4, 1, 2, 0>,
                         cudaFuncAttributeMaxDynamicSharedMemorySize, SM_O64);
    cudaFuncSetAttribute((const void*)attention_kernel,
                         cudaFuncAttributeMaxDynamicSharedMemorySize, NP * HID * 2);

    // ---------------- setup ----------------
    zero_hc_kernel<<<(BATCH * HID) / 256, 256>>>();
    build_wg_kernel<<<(2048 * 1024) / 256, 256>>>(Wih, Whh, bih, bhh);
    build_wlx_kernel<<<(1024 * 512) / 256, 256>>>(Wa, Wc, ba, bc);
    gather_emb_kernel<<<dim3(BATCH, TT), 128>>>(targets, emb_table);
    cvt_weights_kernel<<<592, 256>>>(Wfc, Wa, Wc, Wo);
    cvt_copy_kernel<<<1024, 256>>>(features, p_featcvt, BATCH * NP * CIN / 4);

    // feats (fp16) = features @ Wfc^T + bfc : M=32768, N=512, K=512
    gemm<128, 64, 32, 4, 2, 4, 0><<<dim3(HID / 64, (BATCH * NP) / 128), 256, SM_BIG32>>>(
        p_featcvt, CIN, CIN, nullptr, 0, CIN,
        p_wcvt + OFF_WFC, CIN, 0, bfc, nullptr, 0, p_feats_h, HID, nullptr, 0);

    // pre = emb @ [WaE;WcC]^T + [ba;bc] : M=15360, N=1024, K=512
    gemm<128, 64, 32, 4, 2, 0, 0><<<dim3(1024 / 64, (TT * BATCH) / 128), 256, SM_BIG32>>>(
        p_emb, EMB, EMB, nullptr, 0, EMB,
        p_Wlx, 512, 0, p_blx, nullptr, 0, p_pre, 1024, nullptr, 0);

    // ---------------- 30-step recurrence ----------------
    for (int t = 0; t < TT; t++) {
        float* hr = p_hbuf + (t & 1) * BATCH * HID;
        float* hw = p_hbuf + ((t + 1) & 1) * BATCH * HID;
        const float* pre_t = p_pre + (size_t)t * BATCH * 1024;

        // logits (split-K=2, BK=64): h @ WaH^T + pre[t][:, :512]
        gemm<64, 32, 64, 2, 2, 0, 1><<<dim3(HID / 32, BATCH / 64, 2), 128, SM_S64>>>(
            hr, HID, HID, nullptr, 0, 256,
            p_wcvt + OFF_WA, HID + EMB, 0, nullptr, pre_t, 1024,
            p_logits2, HID, nullptr, 0);

        attention_kernel<<<BATCH, 256, NP * HID * 2>>>(p_ctx);

        // x = ctx @ WcC^T + pre[t][:, 512:], tf32-rounded (BK=64)
        gemm<64, 32, 64, 2, 2, 5, 0><<<dim3(HID / 32, BATCH / 64), 128, SM_S64>>>(
            p_ctx, HID, HID, nullptr, 0, HID,
            p_wcvt + OFF_WC, EMB + HID, 512, nullptr, pre_t + 512, 1024,
            p_x, HID, nullptr, 0);

        // gates = [x,h] @ Wg^T + bg ; fused LSTM (64x64 tiles, 256 CTAs)
        gemm<64, 64, 64, 2, 2, 1, 0><<<dim3((4 * HID) / 64, BATCH / 64), 128, SM_G64>>>(
            p_x, HID, HID, hr, HID, 2 * HID,
            p_Wg, 2 * HID, 0, nullptr, nullptr, 0, nullptr, 0, hw, t);
    }

    // out[b,t,:] = hist @ Wo^T + bo : M=15360, N=96, K=512, permuted write
    gemm<128, 32, 64, 4, 1, 2, 0><<<dim3(NCLS / 32, (TT * BATCH) / 128), 128, SM_O64>>>(
        p_hist, HID, HID, nullptr, 0, HID,
        p_wcvt + OFF_WO, HID, 0, bo, nullptr, 0, out, 0, nullptr, 0);
}

// round 15
// speedup vs baseline: 1.0793x; 1.0072x over previous
#include <cuda_runtime.h>
#include <cuda_fp16.h>
#include <math.h>
#include <stdint.h>

#define BATCH 512
#define NP    64
#define CIN   512
#define HID   512
#define EMB   512
#define NCLS  96
#define TT    30

__device__ float  g_featcvt[(size_t)BATCH * NP * CIN];
__device__ __half g_feats_h[(size_t)BATCH * NP * HID];
__device__ float  g_emb[(size_t)TT * BATCH * EMB];
__device__ float  g_pre[(size_t)TT * BATCH * 1024];
__device__ float  g_hist[(size_t)TT * BATCH * HID];
__device__ float  g_hbuf[2][BATCH * HID];
__device__ float  g_c[BATCH * HID];
__device__ float  g_logits2[2][BATCH * HID];
__device__ float  g_ctx[BATCH * HID];
__device__ float  g_x[BATCH * HID];
__device__ float  g_Wg[(size_t)2048 * 1024];
__device__ float  g_bg[2048];
__device__ float  g_Wlx[(size_t)1024 * 512];
__device__ float  g_blx[1024];
#define OFF_WFC 0
#define OFF_WA  (512 * 512)
#define OFF_WC  (OFF_WA + 512 * 1024)
#define OFF_WO  (OFF_WC + 512 * 1024)
#define WCVT_N  (OFF_WO + 96 * 512)
__device__ float g_wcvt[WCVT_N];

__device__ __forceinline__ float f2tf32f(float f) {
    uint32_t r;
    asm("cvt.rna.tf32.f32 %0, %1;" : "=r"(r) : "f"(f));
    return __uint_as_float(r);
}
__device__ __forceinline__ float fsig(float x) {
    return __fdividef(1.f, 1.f + __expf(-x));
}
__device__ __forceinline__ float ftanh(float x) {
    x = fminf(fmaxf(x, -15.f), 15.f);
    float t = __expf(2.f * x);
    return __fdividef(t - 1.f, t + 1.f);
}
__device__ __forceinline__ void cp16(uint32_t dst, const void* src) {
    asm volatile("cp.async.cg.shared.global [%0], [%1], 16;" :: "r"(dst), "l"(src));
}
__device__ __forceinline__ void cp_commit() { asm volatile("cp.async.commit_group;"); }
template <int N>
__device__ __forceinline__ void cp_wait() { asm volatile("cp.async.wait_group %0;" :: "n"(N)); }

// ------------- TF32 GEMM, cp.async 3-stage + frag double-buffer -----------
// MODE 0: float C = acc (+bias)(+addend[ldadd])
// MODE 1: fused LSTM epilogue
// MODE 2: permuted fp32 out-projection write
// MODE 5: tf32-rounded float C = acc (+bias)(+addend)
// SPLITK: blockIdx.z selects K-half (K passed as 256).
template <int BM, int BN, int BK, int WARPS_M, int WARPS_N, int MODE, int SPLITK>
__global__ void __launch_bounds__(WARPS_M * WARPS_N * 32)
gemm(const float* __restrict__ A1, int lda1, int K1,
     const float* __restrict__ A2, int lda2, int K,
     const float* __restrict__ B, int ldb, int boff,
     const float* __restrict__ bias,
     const float* __restrict__ addend, int ldadd,
     void* __restrict__ Cv, int ldc, float* __restrict__ h_out, int t)
{
    constexpr int S = 3, PAD = 4, ROWF = BK + PAD;
    constexpr int THREADS = WARPS_M * WARPS_N * 32;
    constexpr int WM = BM / WARPS_M, WN = BN / WARPS_N;
    constexpr int M_SUB = WM / 16, N_SUB = WN / 8;
    constexpr int BK4 = BK / 4;
    constexpr int AV = (BM * BK) / (4 * THREADS);
    constexpr int BV = (BN * BK) / (4 * THREADS);
    constexpr int ASTR = BM * ROWF;
    constexpr int BSTR = BN * ROWF;

    if constexpr (SPLITK) {
        if (blockIdx.z) {
            A1 += 256;
            boff += 256;
            Cv = (void*)((float*)Cv + (size_t)BATCH * HID);
            addend = nullptr;
        }
    }

    extern __shared__ float sh[];
    const uint32_t smem_u = (uint32_t)__cvta_generic_to_shared(sh);
    const int bm = blockIdx.y * BM, bn = blockIdx.x * BN;
    const int tid = threadIdx.x;
    const int wid = tid >> 5, lane = tid & 31;
    const int gid = lane >> 2, tig = lane & 3;
    const int warpM = wid % WARPS_M, warpN = wid / WARPS_M;

    float acc[M_SUB][N_SUB][4];
#pragma unroll
    for (int i = 0; i < M_SUB; i++)
#pragma unroll
        for (int j = 0; j < N_SUB; j++)
#pragma unroll
            for (int q = 0; q < 4; q++) acc[i][j][q] = 0.f;

    auto issue = [&](int stg, int k0) {
        const float* Ap; int lda, kc;
        if (k0 < K1) { Ap = A1; lda = lda1; kc = k0; }
        else         { Ap = A2; lda = lda2; kc = k0 - K1; }
        uint32_t ab = smem_u + (uint32_t)(stg * ASTR) * 4u;
#pragma unroll
        for (int i = 0; i < AV; i++) {
            int idx = tid + i * THREADS;
            int r = idx / BK4, c4 = idx % BK4;
            cp16(ab + (uint32_t)(r * ROWF + c4 * 4) * 4u,
                 Ap + (size_t)(bm + r) * lda + kc + c4 * 4);
        }
        uint32_t bb = smem_u + (uint32_t)(S * ASTR + stg * BSTR) * 4u;
#pragma unroll
        for (int i = 0; i < BV; i++) {
            int idx = tid + i * THREADS;
            int r = idx / BK4, c4 = idx % BK4;
            cp16(bb + (uint32_t)(r * ROWF + c4 * 4) * 4u,
                 B + (size_t)(bn + r) * ldb + boff + k0 + c4 * 4);
        }
    };

    const int NK = K / BK;
    issue(0, 0);  cp_commit();
    issue(1, BK); cp_commit();

    uint32_t afr[2][M_SUB][4];
    uint32_t bfr[2][N_SUB][2];
    auto ldfrag = [&](const float* As, const float* Bs, int buf, int kb) {
#pragma unroll
        for (int mt = 0; mt < M_SUB; mt++) {
            int r0 = warpM * WM + mt * 16 + gid;
            afr[buf][mt][0] = __float_as_uint(As[r0 * ROWF + kb + tig]);
            afr[buf][mt][1] = __float_as_uint(As[(r0 + 8) * ROWF + kb + tig]);
            afr[buf][mt][2] = __float_as_uint(As[r0 * ROWF + kb + tig + 4]);
            afr[buf][mt][3] = __float_as_uint(As[(r0 + 8) * ROWF + kb + tig + 4]);
        }
#pragma unroll
        for (int nt = 0; nt < N_SUB; nt++) {
            int c0 = warpN * WN + nt * 8 + gid;
            bfr[buf][nt][0] = __float_as_uint(Bs[c0 * ROWF + kb + tig]);
            bfr[buf][nt][1] = __float_as_uint(Bs[c0 * ROWF + kb + tig + 4]);
        }
    };

    for (int k = 0; k < NK; k++) {
        cp_wait<1>();
        __syncthreads();
        int kn = k + S - 1;
        if (kn < NK) issue(kn % S, kn * BK);
        cp_commit();
        const float* As = sh + (k % S) * ASTR;
        const float* Bs = sh + S * ASTR + (k % S) * BSTR;
        ldfrag(As, Bs, 0, 0);
#pragma unroll
        for (int ks = 0; ks < BK / 8; ks++) {
            const int cur = ks & 1, nxt = cur ^ 1;
            if (ks < BK / 8 - 1) ldfrag(As, Bs, nxt, (ks + 1) * 8);
#pragma unroll
            for (int nt = 0; nt < N_SUB; nt++) {
#pragma unroll
                for (int mt = 0; mt < M_SUB; mt++) {
                    asm volatile(
                        "mma.sync.aligned.m16n8k8.row.col.f32.tf32.tf32.f32 "
                        "{%0,%1,%2,%3}, {%4,%5,%6,%7}, {%8,%9}, {%0,%1,%2,%3};"
                        : "+f"(acc[mt][nt][0]), "+f"(acc[mt][nt][1]),
                          "+f"(acc[mt][nt][2]), "+f"(acc[mt][nt][3])
                        : "r"(afr[cur][mt][0]), "r"(afr[cur][mt][1]),
                          "r"(afr[cur][mt][2]), "r"(afr[cur][mt][3]),
                          "r"(bfr[cur][nt][0]), "r"(bfr[cur][nt][1]));
                }
            }
        }
    }

    if constexpr (MODE == 0 || MODE == 5) {
        float* C = (float*)Cv;
#pragma unroll
        for (int mt = 0; mt < M_SUB; mt++) {
#pragma unroll
            for (int nt = 0; nt < N_SUB; nt++) {
                int row0 = bm + warpM * WM + mt * 16 + gid;
                int col  = bn + warpN * WN + nt * 8 + 2 * tig;
                float bx = 0.f, by = 0.f;
                if (bias) { float2 bv = *(const float2*)(bias + col); bx = bv.x; by = bv.y; }
                float a0x = 0.f, a0y = 0.f, a1x = 0.f, a1y = 0.f;
                if (addend) {
                    float2 v = *(const float2*)(addend + (size_t)row0 * ldadd + col);
                    a0x = v.x; a0y = v.y;
                    float2 w = *(const float2*)(addend + (size_t)(row0 + 8) * ldadd + col);
                    a1x = w.x; a1y = w.y;
                }
                float2 v0 = { acc[mt][nt][0] + bx + a0x, acc[mt][nt][1] + by + a0y };
                float2 v1 = { acc[mt][nt][2] + bx + a1x, acc[mt][nt][3] + by + a1y };
                if (MODE == 5) {
                    v0.x = f2tf32f(v0.x); v0.y = f2tf32f(v0.y);
                    v1.x = f2tf32f(v1.x); v1.y = f2tf32f(v1.y);
                }
                *(float2*)(C + (size_t)row0 * ldc + col) = v0;
                *(float2*)(C + (size_t)(row0 + 8) * ldc + col) = v1;
            }
        }
    } else if constexpr (MODE == 2) {
        float* C = (float*)Cv;
#pragma unroll
        for (int mt = 0; mt < M_SUB; mt++) {
#pragma unroll
            for (int nt = 0; nt < N_SUB; nt++) {
                int row0 = bm + warpM * WM + mt * 16 + gid;
                int col  = bn + warpN * WN + nt * 8 + 2 * tig;
                float2 bv = *(const float2*)(bias + col);
#pragma unroll
                for (int rr = 0; rr < 2; rr++) {
                    int r = row0 + rr * 8;
                    int tt = r >> 9, b = r & 511;
                    *(float2*)(C + ((size_t)b * TT + tt) * NCLS + col) =
                        make_float2(acc[mt][nt][rr * 2 + 0] + bv.x,
                                    acc[mt][nt][rr * 2 + 1] + bv.y);
                }
            }
        }
    } else {  // MODE 1: fused LSTM epilogue
        float* Cs = sh;
        constexpr int CPAD = 4;
        __syncthreads();
#pragma unroll
        for (int mt = 0; mt < M_SUB; mt++) {
#pragma unroll
            for (int nt = 0; nt < N_SUB; nt++) {
                int rl = warpM * WM + mt * 16 + gid;
                int cl = warpN * WN + nt * 8 + 2 * tig;
                float b0 = g_bg[bn + cl], b1 = g_bg[bn + cl + 1];
                Cs[rl * (BN + CPAD) + cl]           = acc[mt][nt][0] + b0;
                Cs[rl * (BN + CPAD) + cl + 1]       = acc[mt][nt][1] + b1;
                Cs[(rl + 8) * (BN + CPAD) + cl]     = acc[mt][nt][2] + b0;
                Cs[(rl + 8) * (BN + CPAD) + cl + 1] = acc[mt][nt][3] + b1;
            }
        }
        __syncthreads();
        constexpr int UNITS = BN / 4;
        for (int it = tid; it < BM * UNITS; it += THREADS) {
            int r = it / UNITS, u = it % UNITS;
            float gi = Cs[r * (BN + CPAD) + 4 * u + 0];
            float gf = Cs[r * (BN + CPAD) + 4 * u + 1];
            float gg = Cs[r * (BN + CPAD) + 4 * u + 2];
            float go = Cs[r * (BN + CPAD) + 4 * u + 3];
            int b = bm + r;
            int j = (bn >> 2) + u;
            int idx = b * HID + j;
            float c = g_c[idx];
            float cn = fsig(gf) * c + fsig(gi) * ftanh(gg);
            g_c[idx] = cn;
            float hn = f2tf32f(fsig(go) * ftanh(cn));
            h_out[idx] = hn;
            g_hist[(size_t)t * BATCH * HID + idx] = hn;
        }
    }
}

// ---- fused upfront GEMM: feats (half out) + pre (float out), one grid ----
__global__ void __launch_bounds__(256)
upfront_kernel(const float* __restrict__ bfc)
{
    constexpr int BM = 128, BN = 64, BK = 32, S = 3, PAD = 4, ROWF = BK + PAD;
    constexpr int THREADS = 256;
    constexpr int WARPS_M = 4;
    constexpr int WM = 32, WN = 32;
    constexpr int M_SUB = 2, N_SUB = 4;
    constexpr int BK4 = BK / 4;
    constexpr int AV = (BM * BK) / (4 * THREADS);
    constexpr int BV = (BN * BK) / (4 * THREADS);
    constexpr int ASTR = BM * ROWF;
    constexpr int BSTR = BN * ROWF;
    constexpr int K = 512;

    // decode tile: blocks [0,2048) feats (8 n-tiles), [2048,3968) pre (16 n-tiles)
    const bool is_pre = (blockIdx.x >= 2048);
    int bm, bn;
    const float *A, *B, *bias;
    if (!is_pre) {
        int i = blockIdx.x;
        bn = (i & 7) * BN;
        bm = (i >> 3) * BM;
        A = g_featcvt; B = g_wcvt + OFF_WFC; bias = bfc;
    } else {
        int i = blockIdx.x - 2048;
        bn = (i & 15) * BN;
        bm = (i >> 4) * BM;
        A = g_emb; B = g_Wlx; bias = g_blx;
    }

    extern __shared__ float sh[];
    const uint32_t smem_u = (uint32_t)__cvta_generic_to_shared(sh);
    const int tid = threadIdx.x;
    const int wid = tid >> 5, lane = tid & 31;
    const int gid = lane >> 2, tig = lane & 3;
    const int warpM = wid % WARPS_M, warpN = wid / WARPS_M;

    float acc[M_SUB][N_SUB][4];
#pragma unroll
    for (int i = 0; i < M_SUB; i++)
#pragma unroll
        for (int j = 0; j < N_SUB; j++)
#pragma unroll
            for (int q = 0; q < 4; q++) acc[i][j][q] = 0.f;

    auto issue = [&](int stg, int k0) {
        uint32_t ab = smem_u + (uint32_t)(stg * ASTR) * 4u;
#pragma unroll
        for (int i = 0; i < AV; i++) {
            int idx = tid + i * THREADS;
            int r = idx / BK4, c4 = idx % BK4;
            cp16(ab + (uint32_t)(r * ROWF + c4 * 4) * 4u,
                 A + (size_t)(bm + r) * 512 + k0 + c4 * 4);
        }
        uint32_t bb = smem_u + (uint32_t)(S * ASTR + stg * BSTR) * 4u;
#pragma unroll
        for (int i = 0; i < BV; i++) {
            int idx = tid + i * THREADS;
            int r = idx / BK4, c4 = idx % BK4;
            cp16(bb + (uint32_t)(r * ROWF + c4 * 4) * 4u,
                 B + (size_t)(bn + r) * 512 + k0 + c4 * 4);
        }
    };

    const int NK = K / BK;
    issue(0, 0);  cp_commit();
    issue(1, BK); cp_commit();

    uint32_t afr[2][M_SUB][4];
    uint32_t bfr[2][N_SUB][2];
    auto ldfrag = [&](const float* As, const float* Bs, int buf, int kb) {
#pragma unroll
        for (int mt = 0; mt < M_SUB; mt++) {
            int r0 = warpM * WM + mt * 16 + gid;
            afr[buf][mt][0] = __float_as_uint(As[r0 * ROWF + kb + tig]);
            afr[buf][mt][1] = __float_as_uint(As[(r0 + 8) * ROWF + kb + tig]);
            afr[buf][mt][2] = __float_as_uint(As[r0 * ROWF + kb + tig + 4]);
            afr[buf][mt][3] = __float_as_uint(As[(r0 + 8) * ROWF + kb + tig + 4]);
        }
#pragma unroll
        for (int nt = 0; nt < N_SUB; nt++) {
            int c0 = warpN * WN + nt * 8 + gid;
            bfr[buf][nt][0] = __float_as_uint(Bs[c0 * ROWF + kb + tig]);
            bfr[buf][nt][1] = __float_as_uint(Bs[c0 * ROWF + kb + tig + 4]);
        }
    };

    for (int k = 0; k < NK; k++) {
        cp_wait<1>();
        __syncthreads();
        int kn = k + S - 1;
        if (kn < NK) issue(kn % S, kn * BK);
        cp_commit();
        const float* As = sh + (k % S) * ASTR;
        const float* Bs = sh + S * ASTR + (k % S) * BSTR;
        ldfrag(As, Bs, 0, 0);
#pragma unroll
        for (int ks = 0; ks < BK / 8; ks++) {
            const int cur = ks & 1, nxt = cur ^ 1;
            if (ks < BK / 8 - 1) ldfrag(As, Bs, nxt, (ks + 1) * 8);
#pragma unroll
            for (int nt = 0; nt < N_SUB; nt++) {
#pragma unroll
                for (int mt = 0; mt < M_SUB; mt++) {
                    asm volatile(
                        "mma.sync.aligned.m16n8k8.row.col.f32.tf32.tf32.f32 "
                        "{%0,%1,%2,%3}, {%4,%5,%6,%7}, {%8,%9}, {%0,%1,%2,%3};"
                        : "+f"(acc[mt][nt][0]), "+f"(acc[mt][nt][1]),
                          "+f"(acc[mt][nt][2]), "+f"(acc[mt][nt][3])
                        : "r"(afr[cur][mt][0]), "r"(afr[cur][mt][1]),
                          "r"(afr[cur][mt][2]), "r"(afr[cur][mt][3]),
                          "r"(bfr[cur][nt][0]), "r"(bfr[cur][nt][1]));
                }
            }
        }
    }

#pragma unroll
    for (int mt = 0; mt < M_SUB; mt++) {
#pragma unroll
        for (int nt = 0; nt < N_SUB; nt++) {
            int row0 = bm + warpM * WM + mt * 16 + gid;
            int col  = bn + warpN * WN + nt * 8 + 2 * tig;
            float2 bv = *(const float2*)(bias + col);
            float x0 = acc[mt][nt][0] + bv.x, y0 = acc[mt][nt][1] + bv.y;
            float x1 = acc[mt][nt][2] + bv.x, y1 = acc[mt][nt][3] + bv.y;
            if (!is_pre) {
                *(__half2*)(g_feats_h + (size_t)row0 * 512 + col) = __floats2half2_rn(x0, y0);
                *(__half2*)(g_feats_h + (size_t)(row0 + 8) * 512 + col) = __floats2half2_rn(x1, y1);
            } else {
                *(float2*)(g_pre + (size_t)row0 * 1024 + col) = make_float2(x0, y0);
                *(float2*)(g_pre + (size_t)(row0 + 8) * 1024 + col) = make_float2(x1, y1);
            }
        }
    }
}

// ---- fused attention: smem-staged fp16 feats, read once -------------------
__global__ void attention_kernel(float* __restrict__ ctx)
{
    extern __shared__ __half sfeat[];
    __shared__ float sa[HID];
    __shared__ float sw[NP];
    __shared__ float red[8];

    const int b = blockIdx.x;
    const int tid = threadIdx.x;
    const int lane = tid & 31, warp = tid >> 5;
    const __half* fb = g_feats_h + (size_t)b * NP * HID;

    {
        uint4* d4 = (uint4*)sfeat;
        const uint4* s4 = (const uint4*)fb;
#pragma unroll
        for (int i = tid; i < NP * HID / 8; i += 256) d4[i] = s4[i];
    }

    const float* l0 = g_logits2[0] + (size_t)b * HID;
    const float* l1 = g_logits2[1] + (size_t)b * HID;
    float v0 = l0[tid] + l1[tid];
    float v1 = l0[tid + 256] + l1[tid + 256];
    float m = fmaxf(v0, v1);
#pragma unroll
    for (int o = 16; o > 0; o >>= 1) m = fmaxf(m, __shfl_xor_sync(~0u, m, o));
    if (lane == 0) red[warp] = m;
    __syncthreads();
    if (tid == 0) {
        float tv = red[0];
#pragma unroll
        for (int i = 1; i < 8; i++) tv = fmaxf(tv, red[i]);
        red[0] = tv;
    }
    __syncthreads();
    m = red[0];
    __syncthreads();
    float e0 = __expf(v0 - m), e1 = __expf(v1 - m);
    float s = e0 + e1;
#pragma unroll
    for (int o = 16; o > 0; o >>= 1) s += __shfl_xor_sync(~0u, s, o);
    if (lane == 0) red[warp] = s;
    __syncthreads();
    if (tid == 0) {
        float tv = 0.f;
#pragma unroll
        for (int i = 0; i < 8; i++) tv += red[i];
        red[0] = tv;
    }
    __syncthreads();
    float inv = __fdividef(1.f, red[0]);
    sa[tid] = e0 * inv;
    sa[tid + 256] = e1 * inv;
    __syncthreads();

    for (int p = warp; p < NP; p += 8) {
        const __half2* fr = (const __half2*)(sfeat + p * HID);
        float sc = 0.f;
#pragma unroll
        for (int e = lane; e < HID / 2; e += 32) {
            float2 f = __half22float2(fr[e]);
            float2 a = *(const float2*)(sa + 2 * e);
            sc += f.x * a.x + f.y * a.y;
        }
#pragma unroll
        for (int o = 16; o > 0; o >>= 1) sc += __shfl_xor_sync(~0u, sc, o);
        if (lane == 0) sw[p] = sc;
    }
    __syncthreads();

    if (tid < 32) {
        float w0 = sw[tid], w1 = sw[tid + 32];
        float mm = fmaxf(w0, w1);
#pragma unroll
        for (int o = 16; o > 0; o >>= 1) mm = fmaxf(mm, __shfl_xor_sync(~0u, mm, o));
        float f0 = __expf(w0 - mm), f1 = __expf(w1 - mm);
        float ss = f0 + f1;
#pragma unroll
        for (int o = 16; o > 0; o >>= 1) ss += __shfl_xor_sync(~0u, ss, o);
        float iv = __fdividef(1.f, ss);
        sw[tid] = f0 * iv;
        sw[tid + 32] = f1 * iv;
    }
    __syncthreads();

    float2 a2 = {0.f, 0.f};
#pragma unroll 8
    for (int p = 0; p < NP; p++) {
        float w = sw[p];
        float2 f = __half22float2(*(const __half2*)(sfeat + p * HID + 2 * tid));
        a2.x += w * f.x;
        a2.y += w * f.y;
    }
    *(float2*)(ctx + (size_t)b * HID + 2 * tid) =
        make_float2(f2tf32f(a2.x), f2tf32f(a2.y));
}

// ---- mega setup: zero + build_wg + build_wlx + gather + cvt (one launch) --
#define SB_ZERO   1024
#define SB_WG     (SB_ZERO + 8192)
#define SB_WLX    (SB_WG + 2048)
#define SB_GATH   (SB_WLX + 7680)
#define SB_WCVT   (SB_GATH + 1328)
#define SB_FEAT   (SB_WCVT + 16384)

__global__ void __launch_bounds__(256)
setup_kernel(const int* __restrict__ targets, const float* __restrict__ table,
             const float* __restrict__ Wih, const float* __restrict__ Whh,
             const float* __restrict__ bih, const float* __restrict__ bhh,
             const float* __restrict__ Wa,  const float* __restrict__ Wc,
             const float* __restrict__ ba,  const float* __restrict__ bc,
             const float* __restrict__ Wfc, const float* __restrict__ Wo,
             const float* __restrict__ features)
{
    const int blk = blockIdx.x;
    const int tid = threadIdx.x;

    if (blk < SB_ZERO) {
        int idx = blk * 256 + tid;
        g_hbuf[0][idx] = 0.f;
        g_c[idx] = 0.f;
    } else if (blk < SB_WG) {
        int idx = (blk - SB_ZERO) * 256 + tid;
        int rn = idx >> 10, k = idx & 1023;
        int j = rn >> 2, gi = rn & 3;
        int orig = gi * 512 + j;
        float v = (k < 512) ? Wih[(size_t)orig * 512 + k]
                            : Whh[(size_t)orig * 512 + (k - 512)];
        g_Wg[idx] = f2tf32f(v);
        if (k == 0) g_bg[rn] = bih[orig] + bhh[orig];
    } else if (blk < SB_WLX) {
        int idx = (blk - SB_WG) * 256 + tid;
        int rn = idx >> 9, k = idx & 511;
        float v = (rn < 512) ? Wa[(size_t)rn * 1024 + 512 + k]
                             : Wc[(size_t)(rn - 512) * 1024 + k];
        g_Wlx[idx] = f2tf32f(v);
        if (k == 0) g_blx[rn] = (rn < 512) ? ba[rn] : bc[rn - 512];
    } else if (blk < SB_GATH) {
        int row = (blk - SB_WLX) * 2 + (tid >> 7);   // 0..15359
        int e = tid & 127;                            // float4 index
        int b = row & 511, t = row >> 9;
        int id = (t == 0) ? 0 : targets[(size_t)b * TT + (t - 1)];
        float4 v = ((const float4*)(table + (size_t)id * EMB))[e];
        v.x = f2tf32f(v.x); v.y = f2tf32f(v.y);
        v.z = f2tf32f(v.z); v.w = f2tf32f(v.w);
        ((float4*)(g_emb + ((size_t)t * BATCH + b) * EMB))[e] = v;
    } else if (blk < SB_WCVT) {
        int i = (blk - SB_GATH) * 256 + tid;
        int e = i * 4;
        const float* src;
        if (e < OFF_WA)      src = Wfc + e;
        else if (e < OFF_WC) src = Wa + (e - OFF_WA);
        else if (e < OFF_WO) src = Wc + (e - OFF_WC);
        else                 src = Wo + (e - OFF_WO);
        float4 v = *(const float4*)src;
        v.x = f2tf32f(v.x); v.y = f2tf32f(v.y);
        v.z = f2tf32f(v.z); v.w = f2tf32f(v.w);
        *(float4*)(g_wcvt + e) = v;
    } else {
        int i = (blk - SB_WCVT) * 256 + tid;
        float4 v = ((const float4*)features)[i];
        v.x = f2tf32f(v.x); v.y = f2tf32f(v.y);
        v.z = f2tf32f(v.z); v.w = f2tf32f(v.w);
        ((float4*)g_featcvt)[i] = v;
    }
}

// ---------------- launch ----------------------------------------------------
extern "C" void kernel_launch(void* const* d_in, const int* in_sizes, int n_in,
                              void* d_out, int out_size)
{
    const float* features  = (const float*)d_in[0];
    const int*   targets   = (const int*)d_in[1];
    const float* Wfc = (const float*)d_in[3];
    const float* bfc = (const float*)d_in[4];
    const float* emb_table = (const float*)d_in[5];
    const float* Wa  = (const float*)d_in[6];
    const float* ba  = (const float*)d_in[7];
    const float* Wc  = (const float*)d_in[8];
    const float* bc  = (const float*)d_in[9];
    const float* Wih = (const float*)d_in[10];
    const float* Whh = (const float*)d_in[11];
    const float* bih = (const float*)d_in[12];
    const float* bhh = (const float*)d_in[13];
    const float* Wo  = (const float*)d_in[14];
    const float* bo  = (const float*)d_in[15];
    float* out = (float*)d_out;

    float *p_pre, *p_hist, *p_hbuf, *p_logits2, *p_ctx, *p_x, *p_Wg, *p_wcvt;
    cudaGetSymbolAddress((void**)&p_pre,     g_pre);
    cudaGetSymbolAddress((void**)&p_hist,    g_hist);
    cudaGetSymbolAddress((void**)&p_hbuf,    g_hbuf);
    cudaGetSymbolAddress((void**)&p_logits2, g_logits2);
    cudaGetSymbolAddress((void**)&p_ctx,     g_ctx);
    cudaGetSymbolAddress((void**)&p_x,       g_x);
    cudaGetSymbolAddress((void**)&p_Wg,      g_Wg);
    cudaGetSymbolAddress((void**)&p_wcvt,    g_wcvt);

    constexpr int SM_BIG32 = 3 * (128 + 64) * 36 * 4;   // 82944  (BK=32, S=3)
    constexpr int SM_G64   = 3 * (64 + 64) * 68 * 4;    // 104448 (BK=64, gates 64x64)
    constexpr int SM_S64   = 3 * (64 + 32) * 68 * 4;    // 78336  (BK=64)
    constexpr int SM_O64   = 3 * (128 + 32) * 68 * 4;   // 130560 (BK=64)

    cudaFuncSetAttribute((const void*)upfront_kernel,
                         cudaFuncAttributeMaxDynamicSharedMemorySize, SM_BIG32);
    cudaFuncSetAttribute((const void*)gemm<64, 32, 64, 2, 2, 0, 1>,
                         cudaFuncAttributeMaxDynamicSharedMemorySize, SM_S64);
    cudaFuncSetAttribute((const void*)gemm<64, 32, 64, 2, 2, 5, 0>,
                         cudaFuncAttributeMaxDynamicSharedMemorySize, SM_S64);
    cudaFuncSetAttribute((const void*)gemm<64, 64, 64, 2, 2, 1, 0>,
                         cudaFuncAttributeMaxDynamicSharedMemorySize, SM_G64);
    cudaFuncSetAttribute((const void*)gemm<128, 32, 64, 4, 1, 2, 0>,
                         cudaFuncAttributeMaxDynamicSharedMemorySize, SM_O64);
    cudaFuncSetAttribute((const void*)attention_kernel,
                         cudaFuncAttributeMaxDynamicSharedMemorySize, NP * HID * 2);

    // ---- one mega-setup launch (all independent prep, parallel) ----
    setup_kernel<<<SB_FEAT, 256>>>(targets, emb_table, Wih, Whh, bih, bhh,
                                   Wa, Wc, ba, bc, Wfc, Wo, features);

    // ---- fused upfront GEMM: feats (fp16) + pre, one grid ----
    upfront_kernel<<<3968, 256, SM_BIG32>>>(bfc);

    // ---------------- 30-step recurrence ----------------
    for (int t = 0; t < TT; t++) {
        float* hr = p_hbuf + (t & 1) * BATCH * HID;
        float* hw = p_hbuf + ((t + 1) & 1) * BATCH * HID;
        const float* pre_t = p_pre + (size_t)t * BATCH * 1024;

        // logits (split-K=2, BK=64): h @ WaH^T + pre[t][:, :512]
        gemm<64, 32, 64, 2, 2, 0, 1><<<dim3(HID / 32, BATCH / 64, 2), 128, SM_S64>>>(
            hr, HID, HID, nullptr, 0, 256,
            p_wcvt + OFF_WA, HID + EMB, 0, nullptr, pre_t, 1024,
            p_logits2, HID, nullptr, 0);

        attention_kernel<<<BATCH, 256, NP * HID * 2>>>(p_ctx);

        // x = ctx @ WcC^T + pre[t][:, 512:], tf32-rounded (BK=64)
        gemm<64, 32, 64, 2, 2, 5, 0><<<dim3(HID / 32, BATCH / 64), 128, SM_S64>>>(
            p_ctx, HID, HID, nullptr, 0, HID,
            p_wcvt + OFF_WC, EMB + HID, 512, nullptr, pre_t + 512, 1024,
            p_x, HID, nullptr, 0);

        // gates = [x,h] @ Wg^T + bg ; fused LSTM (64x64 tiles, 256 CTAs)
        gemm<64, 64, 64, 2, 2, 1, 0><<<dim3((4 * HID) / 64, BATCH / 64), 128, SM_G64>>>(
            p_x, HID, HID, hr, HID, 2 * HID,
            p_Wg, 2 * HID, 0, nullptr, nullptr, 0, nullptr, 0, hw, t);
    }

    // out[b,t,:] = hist @ Wo^T + bo : M=15360, N=96, K=512, permuted write
    gemm<128, 32, 64, 4, 1, 2, 0><<<dim3(NCLS / 32, (TT * BATCH) / 128), 128, SM_O64>>>(
        p_hist, HID, HID, nullptr, 0, HID,
        p_wcvt + OFF_WO, HID, 0, bo, nullptr, 0, out, 0, nullptr, 0);
}